// round 1
// baseline (speedup 1.0000x reference)
#include <cuda_runtime.h>
#include <math.h>

#define NRES 768
#define CSDIM 384
#define CZDIM 128
#define CHDIM 16
#define NHEAD 12
#define PQKN 4
#define PVN 8
#define CATDIM 2112   // 12*(128+16+4*8)
#define PROJD 1152    // 3*192 + 2*144 + 288
#define INFV 100000.0f
#define RSQRT3 0.57735026918962576f
#define PWCONST 0.23570226039551584f  // sqrt(2/(9*4))

// ---------------- scratch (static device allocations) ----------------
__device__ float g_wcat[CSDIM * PROJD];          // 1.77 MB
__device__ float g_proj[NRES * PROJD];           // 3.54 MB
__device__ float g_qf[NRES * NHEAD * 28];
__device__ float g_kf[NRES * NHEAD * 28];
__device__ float g_gq[NRES * NHEAD];
__device__ float g_gk[NRES * NHEAD];
__device__ float g_vcat[NRES * NHEAD * 40];
__device__ float g_att[(size_t)NHEAD * NRES * NRES];  // 28.3 MB, layout [h][q][k]
__device__ float g_opt[NRES * NHEAD * 24];
__device__ float g_cat[NRES * CATDIM];           // 6.5 MB

// ---------------- 1: concat weights ----------------
__global__ void k_concat_w(const float* __restrict__ wq, const float* __restrict__ wk,
                           const float* __restrict__ wv, const float* __restrict__ wqp,
                           const float* __restrict__ wkp, const float* __restrict__ wvp) {
    int i = blockIdx.x * blockDim.x + threadIdx.x;
    if (i >= CSDIM * PROJD) return;
    int c = i / PROJD, col = i % PROJD;
    float v;
    if (col < 192)       v = wq[c * 192 + col];
    else if (col < 384)  v = wk[c * 192 + col - 192];
    else if (col < 576)  v = wv[c * 192 + col - 384];
    else if (col < 720)  v = wqp[c * 144 + col - 576];
    else if (col < 864)  v = wkp[c * 144 + col - 720];
    else                 v = wvp[c * 288 + col - 864];
    g_wcat[i] = v;
}

// ---------------- generic tiled SGEMM: C = A[M,K] @ B[K,N] (+bias) ----------------
// BM=BN=64, BK=16, 256 threads, 4x4 microtile. All dims divide evenly here.
__global__ void __launch_bounds__(256) k_sgemm(const float* __restrict__ A,
                                               const float* __restrict__ B,
                                               float* __restrict__ C,
                                               const float* __restrict__ bias,
                                               int M, int N, int K) {
    __shared__ float As[16][68];
    __shared__ float Bs[16][68];
    int tid = threadIdx.x;
    int tx = tid % 16, ty = tid / 16;
    int m0 = blockIdx.y * 64, n0 = blockIdx.x * 64;
    float acc[4][4] = {};
    for (int k0 = 0; k0 < K; k0 += 16) {
        for (int i = tid; i < 64 * 16; i += 256) {
            int r = i / 16, c = i % 16;
            As[c][r] = A[(size_t)(m0 + r) * K + k0 + c];
        }
        for (int i = tid; i < 16 * 64; i += 256) {
            int r = i / 64, c = i % 64;
            Bs[r][c] = B[(size_t)(k0 + r) * N + n0 + c];
        }
        __syncthreads();
#pragma unroll
        for (int kk = 0; kk < 16; kk++) {
            float4 a4 = *(const float4*)&As[kk][ty * 4];
            float4 b4 = *(const float4*)&Bs[kk][tx * 4];
            float av[4] = {a4.x, a4.y, a4.z, a4.w};
            float bv[4] = {b4.x, b4.y, b4.z, b4.w};
#pragma unroll
            for (int i = 0; i < 4; i++)
#pragma unroll
                for (int j = 0; j < 4; j++) acc[i][j] += av[i] * bv[j];
        }
        __syncthreads();
    }
#pragma unroll
    for (int i = 0; i < 4; i++) {
        int row = m0 + ty * 4 + i;
        float4 o;
        o.x = acc[i][0]; o.y = acc[i][1]; o.z = acc[i][2]; o.w = acc[i][3];
        if (bias) {
            o.x += bias[n0 + tx * 4 + 0];
            o.y += bias[n0 + tx * 4 + 1];
            o.z += bias[n0 + tx * 4 + 2];
            o.w += bias[n0 + tx * 4 + 3];
        }
        *(float4*)&C[(size_t)row * N + n0 + tx * 4] = o;
    }
}

// ---------------- 3: per-residue prep ----------------
__global__ void k_prep(const float* __restrict__ bqp, const float* __restrict__ bkp,
                       const float* __restrict__ bvp, const float* __restrict__ rot,
                       const float* __restrict__ trans, const float* __restrict__ hw) {
    int n = blockIdx.x;
    int tid = threadIdx.x;  // 128 threads
    __shared__ float p[PROJD];
    __shared__ float R[9], T[3], pw[NHEAD];
    for (int i = tid; i < PROJD; i += 128) p[i] = g_proj[(size_t)n * PROJD + i];
    if (tid < 9) R[tid] = rot[n * 9 + tid];
    if (tid < 3) T[tid] = trans[n * 3 + tid];
    if (tid < NHEAD) {
        float x = hw[tid];
        float sp = (x > 20.f) ? x : log1pf(expf(x));
        pw[tid] = PWCONST * sp;
    }
    __syncthreads();
    // scalar q/k/v
    for (int i = tid; i < 192; i += 128) {
        int h = i / 16, c = i % 16;
        g_qf[((size_t)n * NHEAD + h) * 28 + c] = p[i] * 0.25f;          // scalar_w folded
        g_kf[((size_t)n * NHEAD + h) * 28 + c] = p[192 + i];
        g_vcat[((size_t)n * NHEAD + h) * 40 + c] = p[384 + i];
    }
    if (tid < 12) {  // q points
        int h = tid;
        float sq = 0.f;
        float pwh = pw[h];
        for (int pp = 0; pp < PQKN; pp++) {
            float lx = p[576 + h * 12 + 0 + pp] + bqp[h * 12 + 0 + pp];
            float ly = p[576 + h * 12 + 4 + pp] + bqp[h * 12 + 4 + pp];
            float lz = p[576 + h * 12 + 8 + pp] + bqp[h * 12 + 8 + pp];
            float gx = R[0] * lx + R[1] * ly + R[2] * lz + T[0];
            float gy = R[3] * lx + R[4] * ly + R[5] * lz + T[1];
            float gz = R[6] * lx + R[7] * ly + R[8] * lz + T[2];
            float* qo = &g_qf[((size_t)n * NHEAD + h) * 28 + 16 + pp * 3];
            qo[0] = pwh * gx; qo[1] = pwh * gy; qo[2] = pwh * gz;   // pw folded into Q side
            sq += gx * gx + gy * gy + gz * gz;
        }
        g_gq[n * NHEAD + h] = -0.5f * pwh * sq;
    } else if (tid < 24) {  // k points
        int h = tid - 12;
        float sq = 0.f;
        for (int pp = 0; pp < PQKN; pp++) {
            float lx = p[720 + h * 12 + 0 + pp] + bkp[h * 12 + 0 + pp];
            float ly = p[720 + h * 12 + 4 + pp] + bkp[h * 12 + 4 + pp];
            float lz = p[720 + h * 12 + 8 + pp] + bkp[h * 12 + 8 + pp];
            float gx = R[0] * lx + R[1] * ly + R[2] * lz + T[0];
            float gy = R[3] * lx + R[4] * ly + R[5] * lz + T[1];
            float gz = R[6] * lx + R[7] * ly + R[8] * lz + T[2];
            float* ko = &g_kf[((size_t)n * NHEAD + h) * 28 + 16 + pp * 3];
            ko[0] = gx; ko[1] = gy; ko[2] = gz;
            sq += gx * gx + gy * gy + gz * gz;
        }
        g_gk[n * NHEAD + h] = -0.5f * pw[h] * sq;
    } else if (tid < 36) {  // v points
        int h = tid - 24;
        for (int pp = 0; pp < PVN; pp++) {
            float lx = p[864 + h * 24 + 0 + pp] + bvp[h * 24 + 0 + pp];
            float ly = p[864 + h * 24 + 8 + pp] + bvp[h * 24 + 8 + pp];
            float lz = p[864 + h * 24 + 16 + pp] + bvp[h * 24 + 16 + pp];
            float gx = R[0] * lx + R[1] * ly + R[2] * lz + T[0];
            float gy = R[3] * lx + R[4] * ly + R[5] * lz + T[1];
            float gz = R[6] * lx + R[7] * ly + R[8] * lz + T[2];
            float* vo = &g_vcat[((size_t)n * NHEAD + h) * 40 + 16 + pp * 3];
            vo[0] = gx; vo[1] = gy; vo[2] = gz;
        }
    }
}

// ---------------- 4: pair bias (z pass #1) -> g_att[h][q][k] ----------------
__global__ void __launch_bounds__(256) k_bbias(const float* __restrict__ z,
                                               const float* __restrict__ wb,
                                               const float* __restrict__ bb) {
    int q = blockIdx.y;
    int k0 = blockIdx.x * 64;
    int tid = threadIdx.x;
    int w = tid / 32, lane = tid % 32;
    __shared__ float wbs[CZDIM * NHEAD];   // 6 KB
    __shared__ float bbs[NHEAD][64];
    __shared__ float bbias_s[NHEAD];
    for (int i = tid; i < CZDIM * NHEAD; i += 256) wbs[i] = wb[i];
    if (tid < NHEAD) bbias_s[tid] = bb[tid];
    __syncthreads();
    for (int i = 0; i < 8; i++) {
        int kl = w * 8 + i;
        int k = k0 + kl;
        float4 zv = *(const float4*)&z[((size_t)q * NRES + k) * CZDIM + lane * 4];
        float acc[NHEAD];
#pragma unroll
        for (int h = 0; h < NHEAD; h++) acc[h] = 0.f;
        float zz[4] = {zv.x, zv.y, zv.z, zv.w};
#pragma unroll
        for (int cc = 0; cc < 4; cc++) {
            const float* wr = &wbs[(lane * 4 + cc) * NHEAD];
#pragma unroll
            for (int h = 0; h < NHEAD; h++) acc[h] += zz[cc] * wr[h];
        }
#pragma unroll
        for (int h = 0; h < NHEAD; h++) {
            acc[h] += __shfl_xor_sync(0xffffffffu, acc[h], 16);
            acc[h] += __shfl_xor_sync(0xffffffffu, acc[h], 8);
            acc[h] += __shfl_xor_sync(0xffffffffu, acc[h], 4);
            acc[h] += __shfl_xor_sync(0xffffffffu, acc[h], 2);
            acc[h] += __shfl_xor_sync(0xffffffffu, acc[h], 1);
        }
        if (lane == 0) {
#pragma unroll
            for (int h = 0; h < NHEAD; h++) bbs[h][kl] = acc[h] + bbias_s[h];
        }
    }
    __syncthreads();
    for (int i = tid; i < NHEAD * 64; i += 256) {
        int h = i / 64, kk = i % 64;
        g_att[((size_t)h * NRES + q) * NRES + k0 + kk] = bbs[h][kk];
    }
}

// ---------------- 5: logits (28-dim bilinear + additive) in-place ----------------
__global__ void __launch_bounds__(256) k_logits(const float* __restrict__ mask) {
    int h = blockIdx.z, q0 = blockIdx.y * 64, k0 = blockIdx.x * 64;
    __shared__ float Qs[28][64], Ks[28][64];
    __shared__ float gqs[64], gks[64], mqs[64], mks[64];
    int tid = threadIdx.x;
    for (int i = tid; i < 64 * 28; i += 256) {
        int r = i / 28, d = i % 28;
        Qs[d][r] = g_qf[((size_t)(q0 + r) * NHEAD + h) * 28 + d];
        Ks[d][r] = g_kf[((size_t)(k0 + r) * NHEAD + h) * 28 + d];
    }
    if (tid < 64) {
        gqs[tid] = g_gq[(q0 + tid) * NHEAD + h];
        mqs[tid] = mask[q0 + tid];
    } else if (tid < 128) {
        int r = tid - 64;
        gks[r] = g_gk[(k0 + r) * NHEAD + h];
        mks[r] = mask[k0 + r];
    }
    __syncthreads();
    int tx = tid % 16, ty = tid / 16;
    float acc[4][4] = {};
#pragma unroll
    for (int d = 0; d < 28; d++) {
        float4 a4 = *(const float4*)&Qs[d][ty * 4];
        float4 b4 = *(const float4*)&Ks[d][tx * 4];
        float av[4] = {a4.x, a4.y, a4.z, a4.w};
        float bv[4] = {b4.x, b4.y, b4.z, b4.w};
#pragma unroll
        for (int i = 0; i < 4; i++)
#pragma unroll
            for (int j = 0; j < 4; j++) acc[i][j] += av[i] * bv[j];
    }
#pragma unroll
    for (int i = 0; i < 4; i++) {
        int r = ty * 4 + i;
        size_t base = ((size_t)h * NRES + (q0 + r)) * NRES + k0 + tx * 4;
        float4 bbv = *(const float4*)&g_att[base];
        float gq = gqs[r], mq = mqs[r];
        float4 o;
        o.x = (bbv.x + acc[i][0] + gq + gks[tx * 4 + 0] + INFV * (mq * mks[tx * 4 + 0] - 1.f)) * RSQRT3;
        o.y = (bbv.y + acc[i][1] + gq + gks[tx * 4 + 1] + INFV * (mq * mks[tx * 4 + 1] - 1.f)) * RSQRT3;
        o.z = (bbv.z + acc[i][2] + gq + gks[tx * 4 + 2] + INFV * (mq * mks[tx * 4 + 2] - 1.f)) * RSQRT3;
        o.w = (bbv.w + acc[i][3] + gq + gks[tx * 4 + 3] + INFV * (mq * mks[tx * 4 + 3] - 1.f)) * RSQRT3;
        *(float4*)&g_att[base] = o;
    }
}

// ---------------- 6: softmax over k, in place ----------------
__global__ void __launch_bounds__(256) k_softmax() {
    int q = blockIdx.x, h = blockIdx.y;
    float* row = &g_att[((size_t)h * NRES + q) * NRES];
    int tid = threadIdx.x;
    __shared__ float red[256];
    float v[3];
#pragma unroll
    for (int i = 0; i < 3; i++) v[i] = row[tid + i * 256];
    float m = fmaxf(fmaxf(v[0], v[1]), v[2]);
    red[tid] = m;
    __syncthreads();
    for (int s = 128; s > 0; s >>= 1) {
        if (tid < s) red[tid] = fmaxf(red[tid], red[tid + s]);
        __syncthreads();
    }
    float mm = red[0];
    __syncthreads();
    float e[3], sum = 0.f;
#pragma unroll
    for (int i = 0; i < 3; i++) { e[i] = expf(v[i] - mm); sum += e[i]; }
    red[tid] = sum;
    __syncthreads();
    for (int s = 128; s > 0; s >>= 1) {
        if (tid < s) red[tid] += red[tid + s];
        __syncthreads();
    }
    float inv = 1.f / red[0];
#pragma unroll
    for (int i = 0; i < 3; i++) row[tid + i * 256] = e[i] * inv;
}

// ---------------- 7: o_pair (z pass #2) ----------------
__global__ void __launch_bounds__(256) k_opair(const float* __restrict__ z) {
    int q = blockIdx.x;
    int tid = threadIdx.x;
    int tx = tid % 32, ty = tid / 32;  // (32,8)
    __shared__ float a_s[NHEAD][NRES];  // 36 KB
    for (int i = tid; i < NHEAD * NRES; i += 256)
        a_s[i / NRES][i % NRES] = g_att[((size_t)(i / NRES) * NRES + q) * NRES + (i % NRES)];
    __syncthreads();
    float4 acc[NHEAD];
#pragma unroll
    for (int h = 0; h < NHEAD; h++) acc[h] = make_float4(0.f, 0.f, 0.f, 0.f);
    const float4* zr = (const float4*)(z + (size_t)q * NRES * CZDIM);
    for (int k = ty; k < NRES; k += 8) {
        float4 zv = zr[k * 32 + tx];
#pragma unroll
        for (int h = 0; h < NHEAD; h++) {
            float ah = a_s[h][k];
            acc[h].x += ah * zv.x;
            acc[h].y += ah * zv.y;
            acc[h].z += ah * zv.z;
            acc[h].w += ah * zv.w;
        }
    }
    __syncthreads();
    float* red = &a_s[0][0];  // reuse smem: 12*128 floats
    for (int i = tid; i < NHEAD * CZDIM; i += 256) red[i] = 0.f;
    __syncthreads();
    for (int r = 0; r < 8; r++) {
        if (ty == r) {
#pragma unroll
            for (int h = 0; h < NHEAD; h++) {
                red[h * CZDIM + tx * 4 + 0] += acc[h].x;
                red[h * CZDIM + tx * 4 + 1] += acc[h].y;
                red[h * CZDIM + tx * 4 + 2] += acc[h].z;
                red[h * CZDIM + tx * 4 + 3] += acc[h].w;
            }
        }
        __syncthreads();
    }
    for (int i = tid; i < NHEAD * CZDIM; i += 256)
        g_cat[(size_t)q * CATDIM + 576 + i] = red[i];
}

// ---------------- 8: o + o_pt (batched per-head GEMM [768x768]x[768x40]) ----------------
__global__ void __launch_bounds__(320) k_ov() {
    int h = blockIdx.y;
    int q0 = blockIdx.x * 64;
    __shared__ float a_t[64 * 65];
    __shared__ float v_t[64 * 40];
    int tid = threadIdx.x;  // 320
    int ci = tid % 40, qg = tid / 40;  // qg 0..7
    float acc[8] = {};
    for (int k0 = 0; k0 < NRES; k0 += 64) {
        for (int i = tid; i < 4096; i += 320) {
            int r = i / 64, kk = i % 64;
            a_t[r * 65 + kk] = g_att[((size_t)h * NRES + q0 + r) * NRES + k0 + kk];
        }
        for (int i = tid; i < 2560; i += 320) {
            int r = i / 40, j = i % 40;
            v_t[r * 40 + j] = g_vcat[((size_t)(k0 + r) * NHEAD + h) * 40 + j];
        }
        __syncthreads();
#pragma unroll 4
        for (int kk = 0; kk < 64; kk++) {
            float vv = v_t[kk * 40 + ci];
#pragma unroll
            for (int r = 0; r < 8; r++) acc[r] += a_t[(qg * 8 + r) * 65 + kk] * vv;
        }
        __syncthreads();
    }
#pragma unroll
    for (int r = 0; r < 8; r++) {
        int q = q0 + qg * 8 + r;
        if (ci < 16)
            g_cat[(size_t)q * CATDIM + h * 16 + ci] = acc[r];
        else
            g_opt[((size_t)q * NHEAD + h) * 24 + ci - 16] = acc[r];
    }
}

// ---------------- 9: rigid-inverse + norms ----------------
__global__ void k_finalize(const float* __restrict__ rot, const float* __restrict__ trans) {
    int q = blockIdx.x;
    int tid = threadIdx.x;  // 96 threads
    __shared__ float R[9], T[3];
    if (tid < 9) R[tid] = rot[q * 9 + tid];
    if (tid < 3) T[tid] = trans[q * 3 + tid];
    __syncthreads();
    int h = tid / 8, pp = tid % 8;
    const float* o = &g_opt[((size_t)q * NHEAD + h) * 24 + pp * 3];
    float dx = o[0] - T[0], dy = o[1] - T[1], dz = o[2] - T[2];
    float lx = R[0] * dx + R[3] * dy + R[6] * dz;
    float ly = R[1] * dx + R[4] * dy + R[7] * dz;
    float lz = R[2] * dx + R[5] * dy + R[8] * dz;
    float nrm = sqrtf(fmaxf(lx * lx + ly * ly + lz * lz, 1e-16f));
    int col = h * 8 + pp;
    float* cr = &g_cat[(size_t)q * CATDIM];
    cr[192 + col] = lx;
    cr[288 + col] = ly;
    cr[384 + col] = lz;
    cr[480 + col] = nrm;
}

// ---------------- launcher ----------------
extern "C" void kernel_launch(void* const* d_in, const int* in_sizes, int n_in,
                              void* d_out, int out_size) {
    const float* s     = (const float*)d_in[0];
    const float* z     = (const float*)d_in[1];
    const float* mask  = (const float*)d_in[2];
    const float* rot   = (const float*)d_in[3];
    const float* trans = (const float*)d_in[4];
    const float* w_q   = (const float*)d_in[5];
    const float* w_k   = (const float*)d_in[6];
    const float* w_v   = (const float*)d_in[7];
    const float* w_qp  = (const float*)d_in[8];
    const float* b_qp  = (const float*)d_in[9];
    const float* w_kp  = (const float*)d_in[10];
    const float* b_kp  = (const float*)d_in[11];
    const float* w_vp  = (const float*)d_in[12];
    const float* b_vp  = (const float*)d_in[13];
    const float* w_b   = (const float*)d_in[14];
    const float* b_b   = (const float*)d_in[15];
    const float* hw    = (const float*)d_in[16];
    const float* w_out = (const float*)d_in[17];
    const float* b_out = (const float*)d_in[18];
    float* out = (float*)d_out;

    float *p_wcat, *p_proj, *p_cat;
    cudaGetSymbolAddress((void**)&p_wcat, g_wcat);
    cudaGetSymbolAddress((void**)&p_proj, g_proj);
    cudaGetSymbolAddress((void**)&p_cat, g_cat);

    // 1. concat projection weights
    k_concat_w<<<(CSDIM * PROJD + 255) / 256, 256>>>(w_q, w_k, w_v, w_qp, w_kp, w_vp);
    // 2. proj = s @ Wcat     [768 x 1152]
    k_sgemm<<<dim3(PROJD / 64, NRES / 64), 256>>>(s, p_wcat, p_proj, nullptr,
                                                  NRES, PROJD, CSDIM);
    // 3. per-residue prep (fold weights, rigid apply)
    k_prep<<<NRES, 128>>>(b_qp, b_kp, b_vp, rot, trans, hw);
    // 4. pair bias (z pass 1)
    k_bbias<<<dim3(NRES / 64, NRES), 256>>>(z, w_b, b_b);
    // 5. logits
    k_logits<<<dim3(NRES / 64, NRES / 64, NHEAD), 256>>>(mask);
    // 6. softmax over k
    k_softmax<<<dim3(NRES, NHEAD), 256>>>();
    // 7. o_pair (z pass 2)
    k_opair<<<NRES, 256>>>(z);
    // 8. o + o_pt
    k_ov<<<dim3(NRES / 64, NHEAD), 320>>>();
    // 9. rigid inverse + norms
    k_finalize<<<NRES, 96>>>(rot, trans);
    // 10. out = cat @ w_out + b_out   [768 x 384]
    k_sgemm<<<dim3(CSDIM / 64, NRES / 64), 256>>>(p_cat, w_out, out, b_out,
                                                  NRES, CSDIM, CATDIM);
}

// round 2
// speedup vs baseline: 1.1776x; 1.1776x over previous
#include <cuda_runtime.h>
#include <math.h>

#define NRES 768
#define CSDIM 384
#define CZDIM 128
#define CHDIM 16
#define NHEAD 12
#define PQKN 4
#define PVN 8
#define CATDIM 2112   // 12*(128+16+4*8)
#define PROJD 1152    // 3*192 + 2*144 + 288
#define INFV 100000.0f
#define RSQRT3 0.57735026918962576f
#define PWCONST 0.23570226039551584f  // sqrt(2/(9*4))

// ---------------- scratch (static device allocations) ----------------
__device__ float g_wcat[CSDIM * PROJD];          // 1.77 MB
__device__ float g_proj[NRES * PROJD];           // 3.54 MB
__device__ float g_qf[NRES * NHEAD * 28];
__device__ float g_kf[NRES * NHEAD * 28];
__device__ float g_gq[NRES * NHEAD];
__device__ float g_gk[NRES * NHEAD];
__device__ float g_vcat[NRES * NHEAD * 40];
__device__ float g_att[(size_t)NHEAD * NRES * NRES];  // 28.3 MB, layout [h][q][k]
__device__ float g_opt[NRES * NHEAD * 24];
__device__ float g_cat[NRES * CATDIM];           // 6.5 MB

// ---------------- 1: concat weights ----------------
__global__ void k_concat_w(const float* __restrict__ wq, const float* __restrict__ wk,
                           const float* __restrict__ wv, const float* __restrict__ wqp,
                           const float* __restrict__ wkp, const float* __restrict__ wvp) {
    int i = blockIdx.x * blockDim.x + threadIdx.x;
    if (i >= CSDIM * PROJD) return;
    int c = i / PROJD, col = i % PROJD;
    float v;
    if (col < 192)       v = wq[c * 192 + col];
    else if (col < 384)  v = wk[c * 192 + col - 192];
    else if (col < 576)  v = wv[c * 192 + col - 384];
    else if (col < 720)  v = wqp[c * 144 + col - 576];
    else if (col < 864)  v = wkp[c * 144 + col - 720];
    else                 v = wvp[c * 288 + col - 864];
    g_wcat[i] = v;
}

// ---------------- generic tiled SGEMM: C = A[M,K] @ B[K,N] (+bias) ----------------
__global__ void __launch_bounds__(256) k_sgemm(const float* __restrict__ A,
                                               const float* __restrict__ B,
                                               float* __restrict__ C,
                                               const float* __restrict__ bias,
                                               int M, int N, int K) {
    __shared__ float As[16][68];
    __shared__ float Bs[16][68];
    int tid = threadIdx.x;
    int tx = tid % 16, ty = tid / 16;
    int m0 = blockIdx.y * 64, n0 = blockIdx.x * 64;
    float acc[4][4] = {};
    for (int k0 = 0; k0 < K; k0 += 16) {
        for (int i = tid; i < 64 * 16; i += 256) {
            int r = i / 16, c = i % 16;
            As[c][r] = A[(size_t)(m0 + r) * K + k0 + c];
        }
        for (int i = tid; i < 16 * 64; i += 256) {
            int r = i / 64, c = i % 64;
            Bs[r][c] = B[(size_t)(k0 + r) * N + n0 + c];
        }
        __syncthreads();
#pragma unroll
        for (int kk = 0; kk < 16; kk++) {
            float4 a4 = *(const float4*)&As[kk][ty * 4];
            float4 b4 = *(const float4*)&Bs[kk][tx * 4];
            float av[4] = {a4.x, a4.y, a4.z, a4.w};
            float bv[4] = {b4.x, b4.y, b4.z, b4.w};
#pragma unroll
            for (int i = 0; i < 4; i++)
#pragma unroll
                for (int j = 0; j < 4; j++) acc[i][j] += av[i] * bv[j];
        }
        __syncthreads();
    }
#pragma unroll
    for (int i = 0; i < 4; i++) {
        int row = m0 + ty * 4 + i;
        float4 o;
        o.x = acc[i][0]; o.y = acc[i][1]; o.z = acc[i][2]; o.w = acc[i][3];
        if (bias) {
            o.x += bias[n0 + tx * 4 + 0];
            o.y += bias[n0 + tx * 4 + 1];
            o.z += bias[n0 + tx * 4 + 2];
            o.w += bias[n0 + tx * 4 + 3];
        }
        *(float4*)&C[(size_t)row * N + n0 + tx * 4] = o;
    }
}

// ---------------- 3: per-residue prep ----------------
__global__ void k_prep(const float* __restrict__ bqp, const float* __restrict__ bkp,
                       const float* __restrict__ bvp, const float* __restrict__ rot,
                       const float* __restrict__ trans, const float* __restrict__ hw) {
    int n = blockIdx.x;
    int tid = threadIdx.x;  // 128 threads
    __shared__ float p[PROJD];
    __shared__ float R[9], T[3], pw[NHEAD];
    for (int i = tid; i < PROJD; i += 128) p[i] = g_proj[(size_t)n * PROJD + i];
    if (tid < 9) R[tid] = rot[n * 9 + tid];
    if (tid < 3) T[tid] = trans[n * 3 + tid];
    if (tid < NHEAD) {
        float x = hw[tid];
        float sp = (x > 20.f) ? x : log1pf(expf(x));
        pw[tid] = PWCONST * sp;
    }
    __syncthreads();
    for (int i = tid; i < 192; i += 128) {
        int h = i / 16, c = i % 16;
        g_qf[((size_t)n * NHEAD + h) * 28 + c] = p[i] * 0.25f;          // scalar_w folded
        g_kf[((size_t)n * NHEAD + h) * 28 + c] = p[192 + i];
        g_vcat[((size_t)n * NHEAD + h) * 40 + c] = p[384 + i];
    }
    if (tid < 12) {  // q points
        int h = tid;
        float sq = 0.f;
        float pwh = pw[h];
        for (int pp = 0; pp < PQKN; pp++) {
            float lx = p[576 + h * 12 + 0 + pp] + bqp[h * 12 + 0 + pp];
            float ly = p[576 + h * 12 + 4 + pp] + bqp[h * 12 + 4 + pp];
            float lz = p[576 + h * 12 + 8 + pp] + bqp[h * 12 + 8 + pp];
            float gx = R[0] * lx + R[1] * ly + R[2] * lz + T[0];
            float gy = R[3] * lx + R[4] * ly + R[5] * lz + T[1];
            float gz = R[6] * lx + R[7] * ly + R[8] * lz + T[2];
            float* qo = &g_qf[((size_t)n * NHEAD + h) * 28 + 16 + pp * 3];
            qo[0] = pwh * gx; qo[1] = pwh * gy; qo[2] = pwh * gz;   // pw folded into Q side
            sq += gx * gx + gy * gy + gz * gz;
        }
        g_gq[n * NHEAD + h] = -0.5f * pwh * sq;
    } else if (tid < 24) {  // k points
        int h = tid - 12;
        float sq = 0.f;
        for (int pp = 0; pp < PQKN; pp++) {
            float lx = p[720 + h * 12 + 0 + pp] + bkp[h * 12 + 0 + pp];
            float ly = p[720 + h * 12 + 4 + pp] + bkp[h * 12 + 4 + pp];
            float lz = p[720 + h * 12 + 8 + pp] + bkp[h * 12 + 8 + pp];
            float gx = R[0] * lx + R[1] * ly + R[2] * lz + T[0];
            float gy = R[3] * lx + R[4] * ly + R[5] * lz + T[1];
            float gz = R[6] * lx + R[7] * ly + R[8] * lz + T[2];
            float* ko = &g_kf[((size_t)n * NHEAD + h) * 28 + 16 + pp * 3];
            ko[0] = gx; ko[1] = gy; ko[2] = gz;
            sq += gx * gx + gy * gy + gz * gz;
        }
        g_gk[n * NHEAD + h] = -0.5f * pw[h] * sq;
    } else if (tid < 36) {  // v points
        int h = tid - 24;
        for (int pp = 0; pp < PVN; pp++) {
            float lx = p[864 + h * 24 + 0 + pp] + bvp[h * 24 + 0 + pp];
            float ly = p[864 + h * 24 + 8 + pp] + bvp[h * 24 + 8 + pp];
            float lz = p[864 + h * 24 + 16 + pp] + bvp[h * 24 + 16 + pp];
            float gx = R[0] * lx + R[1] * ly + R[2] * lz + T[0];
            float gy = R[3] * lx + R[4] * ly + R[5] * lz + T[1];
            float gz = R[6] * lx + R[7] * ly + R[8] * lz + T[2];
            float* vo = &g_vcat[((size_t)n * NHEAD + h) * 40 + 16 + pp * 3];
            vo[0] = gx; vo[1] = gy; vo[2] = gz;
        }
    }
}

// ---------------- 4: pair bias (z pass #1) -> g_att[h][q][k] ----------------
// One k per thread: all 12 heads accumulate in registers over 128 channels.
// w_b read as broadcast LDS.128 (conflict-free), z read as per-lane float4,
// output written as 12 perfectly-coalesced STG rows. No shuffles, no conflicts.
__global__ void __launch_bounds__(256) k_bbias(const float* __restrict__ z,
                                               const float* __restrict__ wb,
                                               const float* __restrict__ bb) {
    int q = blockIdx.y;
    int k = blockIdx.x * 256 + threadIdx.x;
    __shared__ float wbs[CZDIM * NHEAD];   // 6 KB
    __shared__ float bbs[NHEAD];
    for (int i = threadIdx.x; i < CZDIM * NHEAD; i += 256) wbs[i] = wb[i];
    if (threadIdx.x < NHEAD) bbs[threadIdx.x] = bb[threadIdx.x];
    __syncthreads();
    float acc[NHEAD];
#pragma unroll
    for (int h = 0; h < NHEAD; h++) acc[h] = bbs[h];
    const float4* zr = (const float4*)&z[((size_t)q * NRES + k) * CZDIM];
#pragma unroll 4
    for (int j = 0; j < 32; j++) {
        float4 zv = zr[j];
        const float4* wr = (const float4*)&wbs[j * 48];
        float zz[4] = {zv.x, zv.y, zv.z, zv.w};
#pragma unroll
        for (int cc = 0; cc < 4; cc++) {
#pragma unroll
            for (int h4 = 0; h4 < 3; h4++) {
                float4 wv = wr[cc * 3 + h4];
                acc[h4 * 4 + 0] += zz[cc] * wv.x;
                acc[h4 * 4 + 1] += zz[cc] * wv.y;
                acc[h4 * 4 + 2] += zz[cc] * wv.z;
                acc[h4 * 4 + 3] += zz[cc] * wv.w;
            }
        }
    }
#pragma unroll
    for (int h = 0; h < NHEAD; h++)
        g_att[((size_t)h * NRES + q) * NRES + k] = acc[h];
}

// ---------------- 5: logits (28-dim bilinear + additive) in-place ----------------
__global__ void __launch_bounds__(256) k_logits(const float* __restrict__ mask) {
    int h = blockIdx.z, q0 = blockIdx.y * 64, k0 = blockIdx.x * 64;
    __shared__ float Qs[28][64], Ks[28][64];
    __shared__ float gqs[64], gks[64], mqs[64], mks[64];
    int tid = threadIdx.x;
    for (int i = tid; i < 64 * 28; i += 256) {
        int r = i / 28, d = i % 28;
        Qs[d][r] = g_qf[((size_t)(q0 + r) * NHEAD + h) * 28 + d];
        Ks[d][r] = g_kf[((size_t)(k0 + r) * NHEAD + h) * 28 + d];
    }
    if (tid < 64) {
        gqs[tid] = g_gq[(q0 + tid) * NHEAD + h];
        mqs[tid] = mask[q0 + tid];
    } else if (tid < 128) {
        int r = tid - 64;
        gks[r] = g_gk[(k0 + r) * NHEAD + h];
        mks[r] = mask[k0 + r];
    }
    __syncthreads();
    int tx = tid % 16, ty = tid / 16;
    float acc[4][4] = {};
#pragma unroll
    for (int d = 0; d < 28; d++) {
        float4 a4 = *(const float4*)&Qs[d][ty * 4];
        float4 b4 = *(const float4*)&Ks[d][tx * 4];
        float av[4] = {a4.x, a4.y, a4.z, a4.w};
        float bv[4] = {b4.x, b4.y, b4.z, b4.w};
#pragma unroll
        for (int i = 0; i < 4; i++)
#pragma unroll
            for (int j = 0; j < 4; j++) acc[i][j] += av[i] * bv[j];
    }
#pragma unroll
    for (int i = 0; i < 4; i++) {
        int r = ty * 4 + i;
        size_t base = ((size_t)h * NRES + (q0 + r)) * NRES + k0 + tx * 4;
        float4 bbv = *(const float4*)&g_att[base];
        float gq = gqs[r], mq = mqs[r];
        float4 o;
        o.x = (bbv.x + acc[i][0] + gq + gks[tx * 4 + 0] + INFV * (mq * mks[tx * 4 + 0] - 1.f)) * RSQRT3;
        o.y = (bbv.y + acc[i][1] + gq + gks[tx * 4 + 1] + INFV * (mq * mks[tx * 4 + 1] - 1.f)) * RSQRT3;
        o.z = (bbv.z + acc[i][2] + gq + gks[tx * 4 + 2] + INFV * (mq * mks[tx * 4 + 2] - 1.f)) * RSQRT3;
        o.w = (bbv.w + acc[i][3] + gq + gks[tx * 4 + 3] + INFV * (mq * mks[tx * 4 + 3] - 1.f)) * RSQRT3;
        *(float4*)&g_att[base] = o;
    }
}

// ---------------- 6: softmax over k, in place ----------------
__global__ void __launch_bounds__(256) k_softmax() {
    int q = blockIdx.x, h = blockIdx.y;
    float* row = &g_att[((size_t)h * NRES + q) * NRES];
    int tid = threadIdx.x;
    __shared__ float red[256];
    float v[3];
#pragma unroll
    for (int i = 0; i < 3; i++) v[i] = row[tid + i * 256];
    float m = fmaxf(fmaxf(v[0], v[1]), v[2]);
    red[tid] = m;
    __syncthreads();
    for (int s = 128; s > 0; s >>= 1) {
        if (tid < s) red[tid] = fmaxf(red[tid], red[tid + s]);
        __syncthreads();
    }
    float mm = red[0];
    __syncthreads();
    float e[3], sum = 0.f;
#pragma unroll
    for (int i = 0; i < 3; i++) { e[i] = expf(v[i] - mm); sum += e[i]; }
    red[tid] = sum;
    __syncthreads();
    for (int s = 128; s > 0; s >>= 1) {
        if (tid < s) red[tid] += red[tid + s];
        __syncthreads();
    }
    float inv = 1.f / red[0];
#pragma unroll
    for (int i = 0; i < 3; i++) row[tid + i * 256] = e[i] * inv;
}

// ---------------- 7: o_pair (z pass #2) ----------------
__global__ void __launch_bounds__(256) k_opair(const float* __restrict__ z) {
    int q = blockIdx.x;
    int tid = threadIdx.x;
    int tx = tid % 32, ty = tid / 32;  // (32,8)
    __shared__ float a_s[NHEAD][NRES];  // 36 KB
    for (int i = tid; i < NHEAD * NRES; i += 256)
        a_s[i / NRES][i % NRES] = g_att[((size_t)(i / NRES) * NRES + q) * NRES + (i % NRES)];
    __syncthreads();
    float4 acc[NHEAD];
#pragma unroll
    for (int h = 0; h < NHEAD; h++) acc[h] = make_float4(0.f, 0.f, 0.f, 0.f);
    const float4* zr = (const float4*)(z + (size_t)q * NRES * CZDIM);
    for (int k = ty; k < NRES; k += 8) {
        float4 zv = zr[k * 32 + tx];
#pragma unroll
        for (int h = 0; h < NHEAD; h++) {
            float ah = a_s[h][k];
            acc[h].x += ah * zv.x;
            acc[h].y += ah * zv.y;
            acc[h].z += ah * zv.z;
            acc[h].w += ah * zv.w;
        }
    }
    __syncthreads();
    float* red = &a_s[0][0];  // reuse smem
    for (int i = tid; i < NHEAD * CZDIM; i += 256) red[i] = 0.f;
    __syncthreads();
    for (int r = 0; r < 8; r++) {
        if (ty == r) {
#pragma unroll
            for (int h = 0; h < NHEAD; h++) {
                red[h * CZDIM + tx * 4 + 0] += acc[h].x;
                red[h * CZDIM + tx * 4 + 1] += acc[h].y;
                red[h * CZDIM + tx * 4 + 2] += acc[h].z;
                red[h * CZDIM + tx * 4 + 3] += acc[h].w;
            }
        }
        __syncthreads();
    }
    for (int i = tid; i < NHEAD * CZDIM; i += 256)
        g_cat[(size_t)q * CATDIM + 576 + i] = red[i];
}

// ---------------- 8: o + o_pt (batched per-head GEMM [768x768]x[768x40]) ----------------
__global__ void __launch_bounds__(320) k_ov() {
    int h = blockIdx.y;
    int q0 = blockIdx.x * 64;
    __shared__ float a_t[64 * 65];
    __shared__ float v_t[64 * 40];
    int tid = threadIdx.x;  // 320
    int ci = tid % 40, qg = tid / 40;  // qg 0..7
    float acc[8] = {};
    for (int k0 = 0; k0 < NRES; k0 += 64) {
        for (int i = tid; i < 4096; i += 320) {
            int r = i / 64, kk = i % 64;
            a_t[r * 65 + kk] = g_att[((size_t)h * NRES + q0 + r) * NRES + k0 + kk];
        }
        for (int i = tid; i < 2560; i += 320) {
            int r = i / 40, j = i % 40;
            v_t[r * 40 + j] = g_vcat[((size_t)(k0 + r) * NHEAD + h) * 40 + j];
        }
        __syncthreads();
#pragma unroll 4
        for (int kk = 0; kk < 64; kk++) {
            float vv = v_t[kk * 40 + ci];
#pragma unroll
            for (int r = 0; r < 8; r++) acc[r] += a_t[(qg * 8 + r) * 65 + kk] * vv;
        }
        __syncthreads();
    }
#pragma unroll
    for (int r = 0; r < 8; r++) {
        int q = q0 + qg * 8 + r;
        if (ci < 16)
            g_cat[(size_t)q * CATDIM + h * 16 + ci] = acc[r];
        else
            g_opt[((size_t)q * NHEAD + h) * 24 + ci - 16] = acc[r];
    }
}

// ---------------- 9: rigid-inverse + norms ----------------
__global__ void k_finalize(const float* __restrict__ rot, const float* __restrict__ trans) {
    int q = blockIdx.x;
    int tid = threadIdx.x;  // 96 threads
    __shared__ float R[9], T[3];
    if (tid < 9) R[tid] = rot[q * 9 + tid];
    if (tid < 3) T[tid] = trans[q * 3 + tid];
    __syncthreads();
    int h = tid / 8, pp = tid % 8;
    const float* o = &g_opt[((size_t)q * NHEAD + h) * 24 + pp * 3];
    float dx = o[0] - T[0], dy = o[1] - T[1], dz = o[2] - T[2];
    float lx = R[0] * dx + R[3] * dy + R[6] * dz;
    float ly = R[1] * dx + R[4] * dy + R[7] * dz;
    float lz = R[2] * dx + R[5] * dy + R[8] * dz;
    float nrm = sqrtf(fmaxf(lx * lx + ly * ly + lz * lz, 1e-16f));
    int col = h * 8 + pp;
    float* cr = &g_cat[(size_t)q * CATDIM];
    cr[192 + col] = lx;
    cr[288 + col] = ly;
    cr[384 + col] = lz;
    cr[480 + col] = nrm;
}

// ---------------- launcher ----------------
extern "C" void kernel_launch(void* const* d_in, const int* in_sizes, int n_in,
                              void* d_out, int out_size) {
    const float* s     = (const float*)d_in[0];
    const float* z     = (const float*)d_in[1];
    const float* mask  = (const float*)d_in[2];
    const float* rot   = (const float*)d_in[3];
    const float* trans = (const float*)d_in[4];
    const float* w_q   = (const float*)d_in[5];
    const float* w_k   = (const float*)d_in[6];
    const float* w_v   = (const float*)d_in[7];
    const float* w_qp  = (const float*)d_in[8];
    const float* b_qp  = (const float*)d_in[9];
    const float* w_kp  = (const float*)d_in[10];
    const float* b_kp  = (const float*)d_in[11];
    const float* w_vp  = (const float*)d_in[12];
    const float* b_vp  = (const float*)d_in[13];
    const float* w_b   = (const float*)d_in[14];
    const float* b_b   = (const float*)d_in[15];
    const float* hw    = (const float*)d_in[16];
    const float* w_out = (const float*)d_in[17];
    const float* b_out = (const float*)d_in[18];
    float* out = (float*)d_out;

    float *p_wcat, *p_proj, *p_cat;
    cudaGetSymbolAddress((void**)&p_wcat, g_wcat);
    cudaGetSymbolAddress((void**)&p_proj, g_proj);
    cudaGetSymbolAddress((void**)&p_cat, g_cat);

    k_concat_w<<<(CSDIM * PROJD + 255) / 256, 256>>>(w_q, w_k, w_v, w_qp, w_kp, w_vp);
    k_sgemm<<<dim3(PROJD / 64, NRES / 64), 256>>>(s, p_wcat, p_proj, nullptr,
                                                  NRES, PROJD, CSDIM);
    k_prep<<<NRES, 128>>>(b_qp, b_kp, b_vp, rot, trans, hw);
    k_bbias<<<dim3(NRES / 256, NRES), 256>>>(z, w_b, b_b);
    k_logits<<<dim3(NRES / 64, NRES / 64, NHEAD), 256>>>(mask);
    k_softmax<<<dim3(NRES, NHEAD), 256>>>();
    k_opair<<<NRES, 256>>>(z);
    k_ov<<<dim3(NRES / 64, NHEAD), 320>>>();
    k_finalize<<<NRES, 96>>>(rot, trans);
    k_sgemm<<<dim3(CSDIM / 64, NRES / 64), 256>>>(p_cat, w_out, out, b_out,
                                                  NRES, CSDIM, CATDIM);
}

// round 3
// speedup vs baseline: 1.2067x; 1.0247x over previous
#include <cuda_runtime.h>
#include <math.h>

#define NRES 768
#define CSDIM 384
#define CZDIM 128
#define CHDIM 16
#define NHEAD 12
#define PQKN 4
#define PVN 8
#define CATDIM 2112   // 12*(128+16+4*8)
#define PROJD 1152    // 3*192 + 2*144 + 288
#define INFV 100000.0f
#define RSQRT3 0.57735026918962576f
#define PWCONST 0.23570226039551584f  // sqrt(2/(9*4))

// packed f32x2 helpers (Blackwell FFMA2 path)
#define FFMA2(d, a, b, c) asm("fma.rn.f32x2 %0, %1, %2, %3;" : "=l"(d) : "l"(a), "l"(b), "l"(c))
#define PACK2(d, lo, hi)  asm("mov.b64 %0, {%1, %2};" : "=l"(d) : "f"(lo), "f"(hi))
#define UNPACK2(lo, hi, d) asm("mov.b64 {%0, %1}, %2;" : "=f"(lo), "=f"(hi) : "l"(d))

// ---------------- scratch (static device allocations) ----------------
__device__ float g_wcat[CSDIM * PROJD];
__device__ float g_proj[NRES * PROJD];
__device__ float g_qf[NRES * NHEAD * 28];
__device__ float g_kf[NRES * NHEAD * 28];
__device__ float g_gq[NRES * NHEAD];
__device__ float g_gk[NRES * NHEAD];
__device__ float g_vcat[NRES * NHEAD * 40];
__device__ float g_att[(size_t)NHEAD * NRES * NRES];  // [h][q][k]
__device__ float g_opt[NRES * NHEAD * 24];
__device__ float g_cat[NRES * CATDIM];
__device__ float g_part[3][NRES * CSDIM];             // split-K partials

// ---------------- 1: concat weights ----------------
__global__ void k_concat_w(const float* __restrict__ wq, const float* __restrict__ wk,
                           const float* __restrict__ wv, const float* __restrict__ wqp,
                           const float* __restrict__ wkp, const float* __restrict__ wvp) {
    int i = blockIdx.x * blockDim.x + threadIdx.x;
    if (i >= CSDIM * PROJD) return;
    int c = i / PROJD, col = i % PROJD;
    float v;
    if (col < 192)       v = wq[c * 192 + col];
    else if (col < 384)  v = wk[c * 192 + col - 192];
    else if (col < 576)  v = wv[c * 192 + col - 384];
    else if (col < 720)  v = wqp[c * 144 + col - 576];
    else if (col < 864)  v = wkp[c * 144 + col - 720];
    else                 v = wvp[c * 288 + col - 864];
    g_wcat[i] = v;
}

// ---------------- tiled SGEMM: C = A[M,K(lda)] @ B[K,N] ----------------
__global__ void __launch_bounds__(256) k_sgemm(const float* __restrict__ A, int lda,
                                               const float* __restrict__ B,
                                               float* __restrict__ C,
                                               int M, int N, int K) {
    __shared__ float As[16][68];
    __shared__ float Bs[16][68];
    int tid = threadIdx.x;
    int tx = tid % 16, ty = tid / 16;
    int m0 = blockIdx.y * 64, n0 = blockIdx.x * 64;
    float acc[4][4] = {};
    for (int k0 = 0; k0 < K; k0 += 16) {
        for (int i = tid; i < 64 * 16; i += 256) {
            int r = i / 16, c = i % 16;
            As[c][r] = A[(size_t)(m0 + r) * lda + k0 + c];
        }
        for (int i = tid; i < 16 * 64; i += 256) {
            int r = i / 64, c = i % 64;
            Bs[r][c] = B[(size_t)(k0 + r) * N + n0 + c];
        }
        __syncthreads();
#pragma unroll
        for (int kk = 0; kk < 16; kk++) {
            float4 a4 = *(const float4*)&As[kk][ty * 4];
            float4 b4 = *(const float4*)&Bs[kk][tx * 4];
            float av[4] = {a4.x, a4.y, a4.z, a4.w};
            float bv[4] = {b4.x, b4.y, b4.z, b4.w};
#pragma unroll
            for (int i = 0; i < 4; i++)
#pragma unroll
                for (int j = 0; j < 4; j++) acc[i][j] += av[i] * bv[j];
        }
        __syncthreads();
    }
#pragma unroll
    for (int i = 0; i < 4; i++) {
        int row = m0 + ty * 4 + i;
        float4 o;
        o.x = acc[i][0]; o.y = acc[i][1]; o.z = acc[i][2]; o.w = acc[i][3];
        *(float4*)&C[(size_t)row * N + n0 + tx * 4] = o;
    }
}

// ---------------- reduce split-K partials + bias ----------------
__global__ void k_reduce3(float* __restrict__ out, const float* __restrict__ b_out) {
    int i = blockIdx.x * 256 + threadIdx.x;
    out[i] = g_part[0][i] + g_part[1][i] + g_part[2][i] + b_out[i % CSDIM];
}

// ---------------- 3: per-residue prep ----------------
__global__ void k_prep(const float* __restrict__ bqp, const float* __restrict__ bkp,
                       const float* __restrict__ bvp, const float* __restrict__ rot,
                       const float* __restrict__ trans, const float* __restrict__ hw) {
    int n = blockIdx.x;
    int tid = threadIdx.x;  // 128 threads
    __shared__ float p[PROJD];
    __shared__ float R[9], T[3], pw[NHEAD];
    for (int i = tid; i < PROJD; i += 128) p[i] = g_proj[(size_t)n * PROJD + i];
    if (tid < 9) R[tid] = rot[n * 9 + tid];
    if (tid < 3) T[tid] = trans[n * 3 + tid];
    if (tid < NHEAD) {
        float x = hw[tid];
        float sp = (x > 20.f) ? x : log1pf(expf(x));
        pw[tid] = PWCONST * sp;
    }
    __syncthreads();
    for (int i = tid; i < 192; i += 128) {
        int h = i / 16, c = i % 16;
        g_qf[((size_t)n * NHEAD + h) * 28 + c] = p[i] * 0.25f;
        g_kf[((size_t)n * NHEAD + h) * 28 + c] = p[192 + i];
        g_vcat[((size_t)n * NHEAD + h) * 40 + c] = p[384 + i];
    }
    if (tid < 12) {
        int h = tid;
        float sq = 0.f;
        float pwh = pw[h];
        for (int pp = 0; pp < PQKN; pp++) {
            float lx = p[576 + h * 12 + 0 + pp] + bqp[h * 12 + 0 + pp];
            float ly = p[576 + h * 12 + 4 + pp] + bqp[h * 12 + 4 + pp];
            float lz = p[576 + h * 12 + 8 + pp] + bqp[h * 12 + 8 + pp];
            float gx = R[0] * lx + R[1] * ly + R[2] * lz + T[0];
            float gy = R[3] * lx + R[4] * ly + R[5] * lz + T[1];
            float gz = R[6] * lx + R[7] * ly + R[8] * lz + T[2];
            float* qo = &g_qf[((size_t)n * NHEAD + h) * 28 + 16 + pp * 3];
            qo[0] = pwh * gx; qo[1] = pwh * gy; qo[2] = pwh * gz;
            sq += gx * gx + gy * gy + gz * gz;
        }
        g_gq[n * NHEAD + h] = -0.5f * pwh * sq;
    } else if (tid < 24) {
        int h = tid - 12;
        float sq = 0.f;
        for (int pp = 0; pp < PQKN; pp++) {
            float lx = p[720 + h * 12 + 0 + pp] + bkp[h * 12 + 0 + pp];
            float ly = p[720 + h * 12 + 4 + pp] + bkp[h * 12 + 4 + pp];
            float lz = p[720 + h * 12 + 8 + pp] + bkp[h * 12 + 8 + pp];
            float gx = R[0] * lx + R[1] * ly + R[2] * lz + T[0];
            float gy = R[3] * lx + R[4] * ly + R[5] * lz + T[1];
            float gz = R[6] * lx + R[7] * ly + R[8] * lz + T[2];
            float* ko = &g_kf[((size_t)n * NHEAD + h) * 28 + 16 + pp * 3];
            ko[0] = gx; ko[1] = gy; ko[2] = gz;
            sq += gx * gx + gy * gy + gz * gz;
        }
        g_gk[n * NHEAD + h] = -0.5f * pw[h] * sq;
    } else if (tid < 36) {
        int h = tid - 24;
        for (int pp = 0; pp < PVN; pp++) {
            float lx = p[864 + h * 24 + 0 + pp] + bvp[h * 24 + 0 + pp];
            float ly = p[864 + h * 24 + 8 + pp] + bvp[h * 24 + 8 + pp];
            float lz = p[864 + h * 24 + 16 + pp] + bvp[h * 24 + 16 + pp];
            float gx = R[0] * lx + R[1] * ly + R[2] * lz + T[0];
            float gy = R[3] * lx + R[4] * ly + R[5] * lz + T[1];
            float gz = R[6] * lx + R[7] * ly + R[8] * lz + T[2];
            float* vo = &g_vcat[((size_t)n * NHEAD + h) * 40 + 16 + pp * 3];
            vo[0] = gx; vo[1] = gy; vo[2] = gz;
        }
    }
}

// ---------------- 4: pair bias (z pass #1) -> g_att[h][q][k] ----------------
// Block = one q row. Thread owns k, k+256, k+512. z staged in smem in 8-channel
// chunks (coalesced 128B/warp global loads, odd-stride conflict-free smem).
// 12 heads = 6 packed f32x2 accumulators per k; w_b pairs reused across 3 k's.
__global__ void __launch_bounds__(256) k_bbias(const float* __restrict__ z,
                                               const float* __restrict__ wb,
                                               const float* __restrict__ bb) {
    int q = blockIdx.x;
    int tid = threadIdx.x;
    __shared__ float zbuf[NRES * 9];        // [768 rows][8 cols pad 9] = 27.6 KB
    __shared__ float wbs[CZDIM * NHEAD];    // 6 KB
    __shared__ float bbs[NHEAD];
    for (int i = tid; i < CZDIM * NHEAD; i += 256) wbs[i] = wb[i];
    if (tid < NHEAD) bbs[tid] = bb[tid];
    unsigned long long acc[3][6];
#pragma unroll
    for (int kc = 0; kc < 3; kc++)
#pragma unroll
        for (int p = 0; p < 6; p++) acc[kc][p] = 0ull;

    for (int cc = 0; cc < 16; cc++) {
        __syncthreads();
        // stage z[q][0:768][cc*8:(cc+1)*8]
#pragma unroll
        for (int i = 0; i < 24; i++) {
            int f = tid + i * 256;
            int row = f >> 3, col = f & 7;
            zbuf[row * 9 + col] = z[((size_t)q * NRES + row) * CZDIM + cc * 8 + col];
        }
        __syncthreads();
#pragma unroll
        for (int j = 0; j < 8; j++) {
            const unsigned long long* wp =
                (const unsigned long long*)(wbs + (cc * 8 + j) * NHEAD);
            unsigned long long w2[6];
#pragma unroll
            for (int p = 0; p < 6; p++) w2[p] = wp[p];
#pragma unroll
            for (int kc = 0; kc < 3; kc++) {
                float zv = zbuf[(kc * 256 + tid) * 9 + j];
                unsigned long long zz;
                PACK2(zz, zv, zv);
#pragma unroll
                for (int p = 0; p < 6; p++) FFMA2(acc[kc][p], zz, w2[p], acc[kc][p]);
            }
        }
    }
#pragma unroll
    for (int kc = 0; kc < 3; kc++) {
        int k = kc * 256 + tid;
#pragma unroll
        for (int p = 0; p < 6; p++) {
            float lo, hi;
            UNPACK2(lo, hi, acc[kc][p]);
            g_att[((size_t)(2 * p) * NRES + q) * NRES + k] = lo + bbs[2 * p];
            g_att[((size_t)(2 * p + 1) * NRES + q) * NRES + k] = hi + bbs[2 * p + 1];
        }
    }
}

// ---------------- 5: logits (28-dim bilinear + additive) in-place ----------------
__global__ void __launch_bounds__(256) k_logits(const float* __restrict__ mask) {
    int h = blockIdx.z, q0 = blockIdx.y * 64, k0 = blockIdx.x * 64;
    __shared__ float Qs[28][64], Ks[28][64];
    __shared__ float gqs[64], gks[64], mqs[64], mks[64];
    int tid = threadIdx.x;
    for (int i = tid; i < 64 * 28; i += 256) {
        int r = i / 28, d = i % 28;
        Qs[d][r] = g_qf[((size_t)(q0 + r) * NHEAD + h) * 28 + d];
        Ks[d][r] = g_kf[((size_t)(k0 + r) * NHEAD + h) * 28 + d];
    }
    if (tid < 64) {
        gqs[tid] = g_gq[(q0 + tid) * NHEAD + h];
        mqs[tid] = mask[q0 + tid];
    } else if (tid < 128) {
        int r = tid - 64;
        gks[r] = g_gk[(k0 + r) * NHEAD + h];
        mks[r] = mask[k0 + r];
    }
    __syncthreads();
    int tx = tid % 16, ty = tid / 16;
    float acc[4][4] = {};
#pragma unroll
    for (int d = 0; d < 28; d++) {
        float4 a4 = *(const float4*)&Qs[d][ty * 4];
        float4 b4 = *(const float4*)&Ks[d][tx * 4];
        float av[4] = {a4.x, a4.y, a4.z, a4.w};
        float bv[4] = {b4.x, b4.y, b4.z, b4.w};
#pragma unroll
        for (int i = 0; i < 4; i++)
#pragma unroll
            for (int j = 0; j < 4; j++) acc[i][j] += av[i] * bv[j];
    }
#pragma unroll
    for (int i = 0; i < 4; i++) {
        int r = ty * 4 + i;
        size_t base = ((size_t)h * NRES + (q0 + r)) * NRES + k0 + tx * 4;
        float4 bbv = *(const float4*)&g_att[base];
        float gq = gqs[r], mq = mqs[r];
        float4 o;
        o.x = (bbv.x + acc[i][0] + gq + gks[tx * 4 + 0] + INFV * (mq * mks[tx * 4 + 0] - 1.f)) * RSQRT3;
        o.y = (bbv.y + acc[i][1] + gq + gks[tx * 4 + 1] + INFV * (mq * mks[tx * 4 + 1] - 1.f)) * RSQRT3;
        o.z = (bbv.z + acc[i][2] + gq + gks[tx * 4 + 2] + INFV * (mq * mks[tx * 4 + 2] - 1.f)) * RSQRT3;
        o.w = (bbv.w + acc[i][3] + gq + gks[tx * 4 + 3] + INFV * (mq * mks[tx * 4 + 3] - 1.f)) * RSQRT3;
        *(float4*)&g_att[base] = o;
    }
}

// ---------------- 6: softmax over k, warp per row ----------------
__global__ void __launch_bounds__(256) k_softmax() {
    int rowid = blockIdx.x * 8 + (threadIdx.x >> 5);  // flat (h*NRES + q)
    int lane = threadIdx.x & 31;
    float4* row = (float4*)(g_att + (size_t)rowid * NRES);
    float4 v[6];
#pragma unroll
    for (int i = 0; i < 6; i++) v[i] = row[lane + i * 32];
    float m = -1e30f;
#pragma unroll
    for (int i = 0; i < 6; i++)
        m = fmaxf(m, fmaxf(fmaxf(v[i].x, v[i].y), fmaxf(v[i].z, v[i].w)));
#pragma unroll
    for (int s = 16; s > 0; s >>= 1) m = fmaxf(m, __shfl_xor_sync(0xffffffffu, m, s));
    float sum = 0.f;
#pragma unroll
    for (int i = 0; i < 6; i++) {
        v[i].x = expf(v[i].x - m); v[i].y = expf(v[i].y - m);
        v[i].z = expf(v[i].z - m); v[i].w = expf(v[i].w - m);
        sum += v[i].x + v[i].y + v[i].z + v[i].w;
    }
#pragma unroll
    for (int s = 16; s > 0; s >>= 1) sum += __shfl_xor_sync(0xffffffffu, sum, s);
    float inv = 1.f / sum;
#pragma unroll
    for (int i = 0; i < 6; i++) {
        v[i].x *= inv; v[i].y *= inv; v[i].z *= inv; v[i].w *= inv;
        row[lane + i * 32] = v[i];
    }
}

// ---------------- 7: o_pair (z pass #2), packed f32x2 ----------------
__global__ void __launch_bounds__(256) k_opair(const float* __restrict__ z) {
    int q = blockIdx.x;
    int tid = threadIdx.x;
    int tx = tid % 32, ty = tid / 32;  // (32,8)
    __shared__ float a_s[NHEAD][NRES];  // 36 KB
    for (int i = tid; i < NHEAD * NRES; i += 256)
        a_s[i / NRES][i % NRES] = g_att[((size_t)(i / NRES) * NRES + q) * NRES + (i % NRES)];
    __syncthreads();
    unsigned long long acc2[NHEAD][2];
#pragma unroll
    for (int h = 0; h < NHEAD; h++) { acc2[h][0] = 0ull; acc2[h][1] = 0ull; }
    const ulonglong2* zr = (const ulonglong2*)(z + (size_t)q * NRES * CZDIM);
    for (int k = ty; k < NRES; k += 8) {
        ulonglong2 zv = zr[k * 32 + tx];   // (z0,z1),(z2,z3)
#pragma unroll
        for (int h = 0; h < NHEAD; h++) {
            float ah = a_s[h][k];
            unsigned long long aa;
            PACK2(aa, ah, ah);
            FFMA2(acc2[h][0], aa, zv.x, acc2[h][0]);
            FFMA2(acc2[h][1], aa, zv.y, acc2[h][1]);
        }
    }
    __syncthreads();
    float* red = &a_s[0][0];
    for (int i = tid; i < NHEAD * CZDIM; i += 256) red[i] = 0.f;
    __syncthreads();
    for (int r = 0; r < 8; r++) {
        if (ty == r) {
#pragma unroll
            for (int h = 0; h < NHEAD; h++) {
                float a0, a1, a2, a3;
                UNPACK2(a0, a1, acc2[h][0]);
                UNPACK2(a2, a3, acc2[h][1]);
                red[h * CZDIM + tx * 4 + 0] += a0;
                red[h * CZDIM + tx * 4 + 1] += a1;
                red[h * CZDIM + tx * 4 + 2] += a2;
                red[h * CZDIM + tx * 4 + 3] += a3;
            }
        }
        __syncthreads();
    }
    for (int i = tid; i < NHEAD * CZDIM; i += 256)
        g_cat[(size_t)q * CATDIM + 576 + i] = red[i];
}

// ---------------- 8: o + o_pt, [k][q] transposed a-tile + f32x2 ----------------
__global__ void __launch_bounds__(320) k_ov() {
    int h = blockIdx.y;
    int q0 = blockIdx.x * 64;
    __shared__ float a_t[64 * 68];   // [kk][q pad 68]
    __shared__ float v_t[64 * 40];   // [kk][c]
    int tid = threadIdx.x;           // 320
    int cg = tid % 20, qg = tid / 20;  // cg: 2-channel group (0..19), qg: 4-q group (0..15)
    unsigned long long acc[4] = {0ull, 0ull, 0ull, 0ull};
    for (int k0 = 0; k0 < NRES; k0 += 64) {
        if (k0) __syncthreads();
        for (int i = tid; i < 4096; i += 320) {
            int r = i >> 6, kk = i & 63;
            a_t[kk * 68 + r] = g_att[((size_t)h * NRES + q0 + r) * NRES + k0 + kk];
        }
        for (int i = tid; i < 2560; i += 320) {
            int r = i / 40, j = i % 40;
            v_t[r * 40 + j] = g_vcat[((size_t)(k0 + r) * NHEAD + h) * 40 + j];
        }
        __syncthreads();
#pragma unroll 8
        for (int kk = 0; kk < 64; kk++) {
            float4 a4 = *(const float4*)&a_t[kk * 68 + qg * 4];
            unsigned long long v2 = *(const unsigned long long*)&v_t[kk * 40 + cg * 2];
            unsigned long long d0, d1, d2, d3;
            PACK2(d0, a4.x, a4.x); FFMA2(acc[0], d0, v2, acc[0]);
            PACK2(d1, a4.y, a4.y); FFMA2(acc[1], d1, v2, acc[1]);
            PACK2(d2, a4.z, a4.z); FFMA2(acc[2], d2, v2, acc[2]);
            PACK2(d3, a4.w, a4.w); FFMA2(acc[3], d3, v2, acc[3]);
        }
    }
    int c = cg * 2;
#pragma unroll
    for (int r = 0; r < 4; r++) {
        int q = q0 + qg * 4 + r;
        float lo, hi;
        UNPACK2(lo, hi, acc[r]);
        if (c < 16) {
            g_cat[(size_t)q * CATDIM + h * 16 + c] = lo;
            g_cat[(size_t)q * CATDIM + h * 16 + c + 1] = hi;
        } else {
            float* o = &g_opt[((size_t)q * NHEAD + h) * 24];
            o[c - 16] = lo;
            o[c - 15] = hi;
        }
    }
}

// ---------------- 9: rigid-inverse + norms ----------------
__global__ void k_finalize(const float* __restrict__ rot, const float* __restrict__ trans) {
    int q = blockIdx.x;
    int tid = threadIdx.x;  // 96 threads
    __shared__ float R[9], T[3];
    if (tid < 9) R[tid] = rot[q * 9 + tid];
    if (tid < 3) T[tid] = trans[q * 3 + tid];
    __syncthreads();
    int h = tid / 8, pp = tid % 8;
    const float* o = &g_opt[((size_t)q * NHEAD + h) * 24 + pp * 3];
    float dx = o[0] - T[0], dy = o[1] - T[1], dz = o[2] - T[2];
    float lx = R[0] * dx + R[3] * dy + R[6] * dz;
    float ly = R[1] * dx + R[4] * dy + R[7] * dz;
    float lz = R[2] * dx + R[5] * dy + R[8] * dz;
    float nrm = sqrtf(fmaxf(lx * lx + ly * ly + lz * lz, 1e-16f));
    int col = h * 8 + pp;
    float* cr = &g_cat[(size_t)q * CATDIM];
    cr[192 + col] = lx;
    cr[288 + col] = ly;
    cr[384 + col] = lz;
    cr[480 + col] = nrm;
}

// ---------------- launcher ----------------
extern "C" void kernel_launch(void* const* d_in, const int* in_sizes, int n_in,
                              void* d_out, int out_size) {
    const float* s     = (const float*)d_in[0];
    const float* z     = (const float*)d_in[1];
    const float* mask  = (const float*)d_in[2];
    const float* rot   = (const float*)d_in[3];
    const float* trans = (const float*)d_in[4];
    const float* w_q   = (const float*)d_in[5];
    const float* w_k   = (const float*)d_in[6];
    const float* w_v   = (const float*)d_in[7];
    const float* w_qp  = (const float*)d_in[8];
    const float* b_qp  = (const float*)d_in[9];
    const float* w_kp  = (const float*)d_in[10];
    const float* b_kp  = (const float*)d_in[11];
    const float* w_vp  = (const float*)d_in[12];
    const float* b_vp  = (const float*)d_in[13];
    const float* w_b   = (const float*)d_in[14];
    const float* b_b   = (const float*)d_in[15];
    const float* hw    = (const float*)d_in[16];
    const float* w_out = (const float*)d_in[17];
    const float* b_out = (const float*)d_in[18];
    float* out = (float*)d_out;

    float *p_wcat, *p_proj, *p_cat, *p_part;
    cudaGetSymbolAddress((void**)&p_wcat, g_wcat);
    cudaGetSymbolAddress((void**)&p_proj, g_proj);
    cudaGetSymbolAddress((void**)&p_cat, g_cat);
    cudaGetSymbolAddress((void**)&p_part, g_part);

    k_concat_w<<<(CSDIM * PROJD + 255) / 256, 256>>>(w_q, w_k, w_v, w_qp, w_kp, w_vp);
    k_sgemm<<<dim3(PROJD / 64, NRES / 64), 256>>>(s, CSDIM, p_wcat, p_proj,
                                                  NRES, PROJD, CSDIM);
    k_prep<<<NRES, 128>>>(b_qp, b_kp, b_vp, rot, trans, hw);
    k_bbias<<<NRES, 256>>>(z, w_b, b_b);
    k_logits<<<dim3(NRES / 64, NRES / 64, NHEAD), 256>>>(mask);
    k_softmax<<<NHEAD * NRES / 8, 256>>>();
    k_opair<<<NRES, 256>>>(z);
    k_ov<<<dim3(NRES / 64, NHEAD), 320>>>();
    k_finalize<<<NRES, 96>>>(rot, trans);
    // final GEMM: split-K = 3 (2112 = 3 * 704), then reduce + bias
    for (int sp = 0; sp < 3; sp++) {
        k_sgemm<<<dim3(CSDIM / 64, NRES / 64), 256>>>(
            p_cat + sp * 704, CATDIM, w_out + (size_t)sp * 704 * CSDIM,
            p_part + (size_t)sp * NRES * CSDIM, NRES, CSDIM, 704);
    }
    k_reduce3<<<NRES * CSDIM / 256, 256>>>(out, b_out);
}

// round 4
// speedup vs baseline: 2.1719x; 1.7999x over previous
#include <cuda_runtime.h>
#include <math.h>

#define NRES 768
#define CSDIM 384
#define CZDIM 128
#define CHDIM 16
#define NHEAD 12
#define PQKN 4
#define PVN 8
#define CATDIM 2112   // 12*(128+16+4*8)
#define PROJD 1152    // 3*192 + 2*144 + 288
#define INFV 100000.0f
#define RSQRT3 0.57735026918962576f
#define PWCONST 0.23570226039551584f  // sqrt(2/(9*4))

// packed f32x2 helpers (Blackwell FFMA2 path)
#define FFMA2(d, a, b, c) asm("fma.rn.f32x2 %0, %1, %2, %3;" : "=l"(d) : "l"(a), "l"(b), "l"(c))
#define PACK2(d, lo, hi)  asm("mov.b64 %0, {%1, %2};" : "=l"(d) : "f"(lo), "f"(hi))
#define UNPACK2(lo, hi, d) asm("mov.b64 {%0, %1}, %2;" : "=f"(lo), "=f"(hi) : "l"(d))

// ---------------- scratch (static device allocations) ----------------
__device__ float g_wcat[CSDIM * PROJD];
__device__ float g_proj[NRES * PROJD];
__device__ float g_qf[NRES * NHEAD * 28];
__device__ float g_kf[NRES * NHEAD * 28];
__device__ float g_gq[NRES * NHEAD];
__device__ float g_gk[NRES * NHEAD];
__device__ float g_vcat[NRES * NHEAD * 40];
__device__ float g_att[(size_t)NHEAD * NRES * NRES];  // [h][q][k]
__device__ float g_opt[NRES * NHEAD * 24];
__device__ float g_cat[NRES * CATDIM];
__device__ float g_part[3][NRES * CSDIM];             // split-K partials

// ---------------- 1: concat weights ----------------
__global__ void k_concat_w(const float* __restrict__ wq, const float* __restrict__ wk,
                           const float* __restrict__ wv, const float* __restrict__ wqp,
                           const float* __restrict__ wkp, const float* __restrict__ wvp) {
    int i = blockIdx.x * blockDim.x + threadIdx.x;
    if (i >= CSDIM * PROJD) return;
    int c = i / PROJD, col = i % PROJD;
    float v;
    if (col < 192)       v = wq[c * 192 + col];
    else if (col < 384)  v = wk[c * 192 + col - 192];
    else if (col < 576)  v = wv[c * 192 + col - 384];
    else if (col < 720)  v = wqp[c * 144 + col - 576];
    else if (col < 864)  v = wkp[c * 144 + col - 720];
    else                 v = wvp[c * 288 + col - 864];
    g_wcat[i] = v;
}

// ---------------- tiled SGEMM with register double-buffer ----------------
// C[z][M,N] = A[:, z*K : z*K+K] @ B[z*K : z*K+K, :]   (z = blockIdx.z split)
__global__ void __launch_bounds__(256) k_sgemm(const float* __restrict__ A, int lda,
                                               const float* __restrict__ B,
                                               float* __restrict__ C,
                                               int M, int N, int K) {
    A += (size_t)blockIdx.z * K;
    B += (size_t)blockIdx.z * K * N;
    C += (size_t)blockIdx.z * M * N;
    __shared__ float As[16][68];
    __shared__ float Bs[16][68];
    int tid = threadIdx.x;
    int tx = tid % 16, ty = tid / 16;
    int m0 = blockIdx.y * 64, n0 = blockIdx.x * 64;
    int ar[4], ac[4], br[4], bc[4];
#pragma unroll
    for (int u = 0; u < 4; u++) {
        int i = tid + u * 256;
        ar[u] = i / 16; ac[u] = i % 16;
        br[u] = i / 64; bc[u] = i % 64;
    }
    float pa[4], pb[4];
#pragma unroll
    for (int u = 0; u < 4; u++) {
        pa[u] = A[(size_t)(m0 + ar[u]) * lda + ac[u]];
        pb[u] = B[(size_t)br[u] * N + n0 + bc[u]];
    }
    float acc[4][4] = {};
    for (int k0 = 0; k0 < K; k0 += 16) {
        __syncthreads();
#pragma unroll
        for (int u = 0; u < 4; u++) {
            As[ac[u]][ar[u]] = pa[u];
            Bs[br[u]][bc[u]] = pb[u];
        }
        __syncthreads();
        if (k0 + 16 < K) {
#pragma unroll
            for (int u = 0; u < 4; u++) {
                pa[u] = A[(size_t)(m0 + ar[u]) * lda + k0 + 16 + ac[u]];
                pb[u] = B[(size_t)(k0 + 16 + br[u]) * N + n0 + bc[u]];
            }
        }
#pragma unroll
        for (int kk = 0; kk < 16; kk++) {
            float4 a4 = *(const float4*)&As[kk][ty * 4];
            float4 b4 = *(const float4*)&Bs[kk][tx * 4];
            float av[4] = {a4.x, a4.y, a4.z, a4.w};
            float bv[4] = {b4.x, b4.y, b4.z, b4.w};
#pragma unroll
            for (int i = 0; i < 4; i++)
#pragma unroll
                for (int j = 0; j < 4; j++) acc[i][j] += av[i] * bv[j];
        }
    }
#pragma unroll
    for (int i = 0; i < 4; i++) {
        int row = m0 + ty * 4 + i;
        float4 o;
        o.x = acc[i][0]; o.y = acc[i][1]; o.z = acc[i][2]; o.w = acc[i][3];
        *(float4*)&C[(size_t)row * N + n0 + tx * 4] = o;
    }
}

// ---------------- reduce split-K partials + bias ----------------
__global__ void k_reduce3(float* __restrict__ out, const float* __restrict__ b_out) {
    int i = blockIdx.x * 256 + threadIdx.x;
    out[i] = g_part[0][i] + g_part[1][i] + g_part[2][i] + b_out[i % CSDIM];
}

// ---------------- 3: per-residue prep ----------------
__global__ void k_prep(const float* __restrict__ bqp, const float* __restrict__ bkp,
                       const float* __restrict__ bvp, const float* __restrict__ rot,
                       const float* __restrict__ trans, const float* __restrict__ hw) {
    int n = blockIdx.x;
    int tid = threadIdx.x;  // 128 threads
    __shared__ float p[PROJD];
    __shared__ float R[9], T[3], pw[NHEAD];
    for (int i = tid; i < PROJD; i += 128) p[i] = g_proj[(size_t)n * PROJD + i];
    if (tid < 9) R[tid] = rot[n * 9 + tid];
    if (tid < 3) T[tid] = trans[n * 3 + tid];
    if (tid < NHEAD) {
        float x = hw[tid];
        float sp = (x > 20.f) ? x : log1pf(expf(x));
        pw[tid] = PWCONST * sp;
    }
    __syncthreads();
    for (int i = tid; i < 192; i += 128) {
        int h = i / 16, c = i % 16;
        g_qf[((size_t)n * NHEAD + h) * 28 + c] = p[i] * 0.25f;
        g_kf[((size_t)n * NHEAD + h) * 28 + c] = p[192 + i];
        g_vcat[((size_t)n * NHEAD + h) * 40 + c] = p[384 + i];
    }
    if (tid < 12) {
        int h = tid;
        float sq = 0.f;
        float pwh = pw[h];
        for (int pp = 0; pp < PQKN; pp++) {
            float lx = p[576 + h * 12 + 0 + pp] + bqp[h * 12 + 0 + pp];
            float ly = p[576 + h * 12 + 4 + pp] + bqp[h * 12 + 4 + pp];
            float lz = p[576 + h * 12 + 8 + pp] + bqp[h * 12 + 8 + pp];
            float gx = R[0] * lx + R[1] * ly + R[2] * lz + T[0];
            float gy = R[3] * lx + R[4] * ly + R[5] * lz + T[1];
            float gz = R[6] * lx + R[7] * ly + R[8] * lz + T[2];
            float* qo = &g_qf[((size_t)n * NHEAD + h) * 28 + 16 + pp * 3];
            qo[0] = pwh * gx; qo[1] = pwh * gy; qo[2] = pwh * gz;
            sq += gx * gx + gy * gy + gz * gz;
        }
        g_gq[n * NHEAD + h] = -0.5f * pwh * sq;
    } else if (tid < 24) {
        int h = tid - 12;
        float sq = 0.f;
        for (int pp = 0; pp < PQKN; pp++) {
            float lx = p[720 + h * 12 + 0 + pp] + bkp[h * 12 + 0 + pp];
            float ly = p[720 + h * 12 + 4 + pp] + bkp[h * 12 + 4 + pp];
            float lz = p[720 + h * 12 + 8 + pp] + bkp[h * 12 + 8 + pp];
            float gx = R[0] * lx + R[1] * ly + R[2] * lz + T[0];
            float gy = R[3] * lx + R[4] * ly + R[5] * lz + T[1];
            float gz = R[6] * lx + R[7] * ly + R[8] * lz + T[2];
            float* ko = &g_kf[((size_t)n * NHEAD + h) * 28 + 16 + pp * 3];
            ko[0] = gx; ko[1] = gy; ko[2] = gz;
            sq += gx * gx + gy * gy + gz * gz;
        }
        g_gk[n * NHEAD + h] = -0.5f * pw[h] * sq;
    } else if (tid < 36) {
        int h = tid - 24;
        for (int pp = 0; pp < PVN; pp++) {
            float lx = p[864 + h * 24 + 0 + pp] + bvp[h * 24 + 0 + pp];
            float ly = p[864 + h * 24 + 8 + pp] + bvp[h * 24 + 8 + pp];
            float lz = p[864 + h * 24 + 16 + pp] + bvp[h * 24 + 16 + pp];
            float gx = R[0] * lx + R[1] * ly + R[2] * lz + T[0];
            float gy = R[3] * lx + R[4] * ly + R[5] * lz + T[1];
            float gz = R[6] * lx + R[7] * ly + R[8] * lz + T[2];
            float* vo = &g_vcat[((size_t)n * NHEAD + h) * 40 + 16 + pp * 3];
            vo[0] = gx; vo[1] = gy; vo[2] = gz;
        }
    }
}

// ---------------- 4: pair bias (z pass #1) -> g_att[h][q][k] ----------------
// Block = one q row, 384 threads, 2 k per thread (k = tid, tid+384).
// 12 heads = 6 packed f32x2 accumulators per k (24 regs total).
// z staged in smem in 8-channel chunks; w_b pairs amortized over 2 k.
__global__ void __launch_bounds__(384, 2) k_bbias(const float* __restrict__ z,
                                                  const float* __restrict__ wb,
                                                  const float* __restrict__ bb) {
    int q = blockIdx.x;
    int tid = threadIdx.x;
    __shared__ float zbuf[NRES * 9];        // 27 KB
    __shared__ float wbs[CZDIM * NHEAD];    // 6 KB
    __shared__ float bbs[NHEAD];
    for (int i = tid; i < CZDIM * NHEAD; i += 384) wbs[i] = wb[i];
    if (tid < NHEAD) bbs[tid] = bb[tid];
    unsigned long long acc[2][6];
#pragma unroll
    for (int kc = 0; kc < 2; kc++)
#pragma unroll
        for (int p = 0; p < 6; p++) acc[kc][p] = 0ull;

    for (int cc = 0; cc < 16; cc++) {
        __syncthreads();
        // stage z[q][0:768][cc*8:(cc+1)*8]
#pragma unroll 4
        for (int j = 0; j < 16; j++) {
            int f = tid + j * 384;
            int row = f >> 3, col = f & 7;
            zbuf[row * 9 + col] = z[((size_t)q * NRES + row) * CZDIM + cc * 8 + col];
        }
        __syncthreads();
#pragma unroll
        for (int j = 0; j < 8; j++) {
            const unsigned long long* wp =
                (const unsigned long long*)(wbs + (cc * 8 + j) * NHEAD);
            unsigned long long w2[6];
#pragma unroll
            for (int p = 0; p < 6; p++) w2[p] = wp[p];
#pragma unroll
            for (int kc = 0; kc < 2; kc++) {
                float zv = zbuf[(kc * 384 + tid) * 9 + j];
                unsigned long long zz;
                PACK2(zz, zv, zv);
#pragma unroll
                for (int p = 0; p < 6; p++) FFMA2(acc[kc][p], zz, w2[p], acc[kc][p]);
            }
        }
    }
#pragma unroll
    for (int kc = 0; kc < 2; kc++) {
        int k = kc * 384 + tid;
#pragma unroll
        for (int p = 0; p < 6; p++) {
            float lo, hi;
            UNPACK2(lo, hi, acc[kc][p]);
            g_att[((size_t)(2 * p) * NRES + q) * NRES + k] = lo + bbs[2 * p];
            g_att[((size_t)(2 * p + 1) * NRES + q) * NRES + k] = hi + bbs[2 * p + 1];
        }
    }
}

// ---------------- 5: logits (28-dim bilinear + additive) in-place ----------------
__global__ void __launch_bounds__(256) k_logits(const float* __restrict__ mask) {
    int h = blockIdx.z, q0 = blockIdx.y * 64, k0 = blockIdx.x * 64;
    __shared__ float Qs[28][64], Ks[28][64];
    __shared__ float gqs[64], gks[64], mqs[64], mks[64];
    int tid = threadIdx.x;
    for (int i = tid; i < 64 * 28; i += 256) {
        int r = i / 28, d = i % 28;
        Qs[d][r] = g_qf[((size_t)(q0 + r) * NHEAD + h) * 28 + d];
        Ks[d][r] = g_kf[((size_t)(k0 + r) * NHEAD + h) * 28 + d];
    }
    if (tid < 64) {
        gqs[tid] = g_gq[(q0 + tid) * NHEAD + h];
        mqs[tid] = mask[q0 + tid];
    } else if (tid < 128) {
        int r = tid - 64;
        gks[r] = g_gk[(k0 + r) * NHEAD + h];
        mks[r] = mask[k0 + r];
    }
    __syncthreads();
    int tx = tid % 16, ty = tid / 16;
    float acc[4][4] = {};
#pragma unroll
    for (int d = 0; d < 28; d++) {
        float4 a4 = *(const float4*)&Qs[d][ty * 4];
        float4 b4 = *(const float4*)&Ks[d][tx * 4];
        float av[4] = {a4.x, a4.y, a4.z, a4.w};
        float bv[4] = {b4.x, b4.y, b4.z, b4.w};
#pragma unroll
        for (int i = 0; i < 4; i++)
#pragma unroll
            for (int j = 0; j < 4; j++) acc[i][j] += av[i] * bv[j];
    }
#pragma unroll
    for (int i = 0; i < 4; i++) {
        int r = ty * 4 + i;
        size_t base = ((size_t)h * NRES + (q0 + r)) * NRES + k0 + tx * 4;
        float4 bbv = *(const float4*)&g_att[base];
        float gq = gqs[r], mq = mqs[r];
        float4 o;
        o.x = (bbv.x + acc[i][0] + gq + gks[tx * 4 + 0] + INFV * (mq * mks[tx * 4 + 0] - 1.f)) * RSQRT3;
        o.y = (bbv.y + acc[i][1] + gq + gks[tx * 4 + 1] + INFV * (mq * mks[tx * 4 + 1] - 1.f)) * RSQRT3;
        o.z = (bbv.z + acc[i][2] + gq + gks[tx * 4 + 2] + INFV * (mq * mks[tx * 4 + 2] - 1.f)) * RSQRT3;
        o.w = (bbv.w + acc[i][3] + gq + gks[tx * 4 + 3] + INFV * (mq * mks[tx * 4 + 3] - 1.f)) * RSQRT3;
        *(float4*)&g_att[base] = o;
    }
}

// ---------------- 6: softmax over k, warp per row ----------------
__global__ void __launch_bounds__(256) k_softmax() {
    int rowid = blockIdx.x * 8 + (threadIdx.x >> 5);  // flat (h*NRES + q)
    int lane = threadIdx.x & 31;
    float4* row = (float4*)(g_att + (size_t)rowid * NRES);
    float4 v[6];
#pragma unroll
    for (int i = 0; i < 6; i++) v[i] = row[lane + i * 32];
    float m = -1e30f;
#pragma unroll
    for (int i = 0; i < 6; i++)
        m = fmaxf(m, fmaxf(fmaxf(v[i].x, v[i].y), fmaxf(v[i].z, v[i].w)));
#pragma unroll
    for (int s = 16; s > 0; s >>= 1) m = fmaxf(m, __shfl_xor_sync(0xffffffffu, m, s));
    float sum = 0.f;
#pragma unroll
    for (int i = 0; i < 6; i++) {
        v[i].x = __expf(v[i].x - m); v[i].y = __expf(v[i].y - m);
        v[i].z = __expf(v[i].z - m); v[i].w = __expf(v[i].w - m);
        sum += v[i].x + v[i].y + v[i].z + v[i].w;
    }
#pragma unroll
    for (int s = 16; s > 0; s >>= 1) sum += __shfl_xor_sync(0xffffffffu, sum, s);
    float inv = 1.f / sum;
#pragma unroll
    for (int i = 0; i < 6; i++) {
        v[i].x *= inv; v[i].y *= inv; v[i].z *= inv; v[i].w *= inv;
        row[lane + i * 32] = v[i];
    }
}

// ---------------- 7: o_pair (z pass #2), packed f32x2, MLP 2 ----------------
__global__ void __launch_bounds__(256) k_opair(const float* __restrict__ z) {
    int q = blockIdx.x;
    int tid = threadIdx.x;
    int tx = tid % 32, ty = tid / 32;  // (32,8)
    __shared__ float a_s[NHEAD][NRES];  // 36 KB
    for (int i = tid; i < NHEAD * NRES; i += 256)
        a_s[i / NRES][i % NRES] = g_att[((size_t)(i / NRES) * NRES + q) * NRES + (i % NRES)];
    __syncthreads();
    unsigned long long acc2[NHEAD][2];
#pragma unroll
    for (int h = 0; h < NHEAD; h++) { acc2[h][0] = 0ull; acc2[h][1] = 0ull; }
    const ulonglong2* zr = (const ulonglong2*)(z + (size_t)q * NRES * CZDIM);
    for (int k = ty; k < NRES; k += 16) {
        ulonglong2 zv0 = zr[k * 32 + tx];
        ulonglong2 zv1 = zr[(k + 8) * 32 + tx];
#pragma unroll
        for (int h = 0; h < NHEAD; h++) {
            float ah = a_s[h][k];
            unsigned long long aa;
            PACK2(aa, ah, ah);
            FFMA2(acc2[h][0], aa, zv0.x, acc2[h][0]);
            FFMA2(acc2[h][1], aa, zv0.y, acc2[h][1]);
        }
#pragma unroll
        for (int h = 0; h < NHEAD; h++) {
            float ah = a_s[h][k + 8];
            unsigned long long aa;
            PACK2(aa, ah, ah);
            FFMA2(acc2[h][0], aa, zv1.x, acc2[h][0]);
            FFMA2(acc2[h][1], aa, zv1.y, acc2[h][1]);
        }
    }
    __syncthreads();
    float* red = &a_s[0][0];
    for (int i = tid; i < NHEAD * CZDIM; i += 256) red[i] = 0.f;
    __syncthreads();
    for (int r = 0; r < 8; r++) {
        if (ty == r) {
#pragma unroll
            for (int h = 0; h < NHEAD; h++) {
                float a0, a1, a2, a3;
                UNPACK2(a0, a1, acc2[h][0]);
                UNPACK2(a2, a3, acc2[h][1]);
                red[h * CZDIM + tx * 4 + 0] += a0;
                red[h * CZDIM + tx * 4 + 1] += a1;
                red[h * CZDIM + tx * 4 + 2] += a2;
                red[h * CZDIM + tx * 4 + 3] += a3;
            }
        }
        __syncthreads();
    }
    for (int i = tid; i < NHEAD * CZDIM; i += 256)
        g_cat[(size_t)q * CATDIM + 576 + i] = red[i];
}

// ---------------- 8: o + o_pt, BQ=32, [k][q] a-tile + f32x2 ----------------
__global__ void __launch_bounds__(320) k_ov() {
    int h = blockIdx.y;
    int q0 = blockIdx.x * 32;
    __shared__ float a_t[64 * 37];   // [kk][q pad 37]
    __shared__ float v_t[64 * 40];   // [kk][c]
    int tid = threadIdx.x;           // 320
    int cg = tid % 20, qg = tid / 20;  // cg: 2-channel group, qg: 2-q group (0..15)
    unsigned long long acc[2] = {0ull, 0ull};
    for (int k0 = 0; k0 < NRES; k0 += 64) {
        if (k0) __syncthreads();
        for (int i = tid; i < 2048; i += 320) {
            int kk = i & 63, r = i >> 6;
            a_t[kk * 37 + r] = g_att[((size_t)h * NRES + q0 + r) * NRES + k0 + kk];
        }
        for (int i = tid; i < 2560; i += 320) {
            int r = i / 40, j = i % 40;
            v_t[r * 40 + j] = g_vcat[((size_t)(k0 + r) * NHEAD + h) * 40 + j];
        }
        __syncthreads();
#pragma unroll 8
        for (int kk = 0; kk < 64; kk++) {
            float a0 = a_t[kk * 37 + qg * 2];
            float a1 = a_t[kk * 37 + qg * 2 + 1];
            unsigned long long v2 = *(const unsigned long long*)&v_t[kk * 40 + cg * 2];
            unsigned long long d0, d1;
            PACK2(d0, a0, a0); FFMA2(acc[0], d0, v2, acc[0]);
            PACK2(d1, a1, a1); FFMA2(acc[1], d1, v2, acc[1]);
        }
    }
    int c = cg * 2;
#pragma unroll
    for (int r = 0; r < 2; r++) {
        int q = q0 + qg * 2 + r;
        float lo, hi;
        UNPACK2(lo, hi, acc[r]);
        if (c < 16) {
            g_cat[(size_t)q * CATDIM + h * 16 + c] = lo;
            g_cat[(size_t)q * CATDIM + h * 16 + c + 1] = hi;
        } else {
            float* o = &g_opt[((size_t)q * NHEAD + h) * 24];
            o[c - 16] = lo;
            o[c - 15] = hi;
        }
    }
}

// ---------------- 9: rigid-inverse + norms ----------------
__global__ void k_finalize(const float* __restrict__ rot, const float* __restrict__ trans) {
    int q = blockIdx.x;
    int tid = threadIdx.x;  // 96 threads
    __shared__ float R[9], T[3];
    if (tid < 9) R[tid] = rot[q * 9 + tid];
    if (tid < 3) T[tid] = trans[q * 3 + tid];
    __syncthreads();
    int h = tid / 8, pp = tid % 8;
    const float* o = &g_opt[((size_t)q * NHEAD + h) * 24 + pp * 3];
    float dx = o[0] - T[0], dy = o[1] - T[1], dz = o[2] - T[2];
    float lx = R[0] * dx + R[3] * dy + R[6] * dz;
    float ly = R[1] * dx + R[4] * dy + R[7] * dz;
    float lz = R[2] * dx + R[5] * dy + R[8] * dz;
    float nrm = sqrtf(fmaxf(lx * lx + ly * ly + lz * lz, 1e-16f));
    int col = h * 8 + pp;
    float* cr = &g_cat[(size_t)q * CATDIM];
    cr[192 + col] = lx;
    cr[288 + col] = ly;
    cr[384 + col] = lz;
    cr[480 + col] = nrm;
}

// ---------------- launcher ----------------
extern "C" void kernel_launch(void* const* d_in, const int* in_sizes, int n_in,
                              void* d_out, int out_size) {
    const float* s     = (const float*)d_in[0];
    const float* z     = (const float*)d_in[1];
    const float* mask  = (const float*)d_in[2];
    const float* rot   = (const float*)d_in[3];
    const float* trans = (const float*)d_in[4];
    const float* w_q   = (const float*)d_in[5];
    const float* w_k   = (const float*)d_in[6];
    const float* w_v   = (const float*)d_in[7];
    const float* w_qp  = (const float*)d_in[8];
    const float* b_qp  = (const float*)d_in[9];
    const float* w_kp  = (const float*)d_in[10];
    const float* b_kp  = (const float*)d_in[11];
    const float* w_vp  = (const float*)d_in[12];
    const float* b_vp  = (const float*)d_in[13];
    const float* w_b   = (const float*)d_in[14];
    const float* b_b   = (const float*)d_in[15];
    const float* hw    = (const float*)d_in[16];
    const float* w_out = (const float*)d_in[17];
    const float* b_out = (const float*)d_in[18];
    float* out = (float*)d_out;

    float *p_wcat, *p_proj, *p_cat, *p_part;
    cudaGetSymbolAddress((void**)&p_wcat, g_wcat);
    cudaGetSymbolAddress((void**)&p_proj, g_proj);
    cudaGetSymbolAddress((void**)&p_cat, g_cat);
    cudaGetSymbolAddress((void**)&p_part, g_part);

    k_concat_w<<<(CSDIM * PROJD + 255) / 256, 256>>>(w_q, w_k, w_v, w_qp, w_kp, w_vp);
    k_sgemm<<<dim3(PROJD / 64, NRES / 64, 1), 256>>>(s, CSDIM, p_wcat, p_proj,
                                                     NRES, PROJD, CSDIM);
    k_prep<<<NRES, 128>>>(b_qp, b_kp, b_vp, rot, trans, hw);
    k_bbias<<<NRES, 384>>>(z, w_b, b_b);
    k_logits<<<dim3(NRES / 64, NRES / 64, NHEAD), 256>>>(mask);
    k_softmax<<<NHEAD * NRES / 8, 256>>>();
    k_opair<<<NRES, 256>>>(z);
    k_ov<<<dim3(NRES / 32, NHEAD), 320>>>();
    k_finalize<<<NRES, 96>>>(rot, trans);
    // final GEMM: split-K = 3 (2112 = 3 * 704) in one 3D launch, then reduce + bias
    k_sgemm<<<dim3(CSDIM / 64, NRES / 64, 3), 256>>>(p_cat, CATDIM, w_out,
                                                     p_part, NRES, CSDIM, 704);
    k_reduce3<<<NRES * CSDIM / 256, 256>>>(out, b_out);
}

// round 9
// speedup vs baseline: 2.2520x; 1.0369x over previous
#include <cuda_runtime.h>
#include <math.h>

#define NRES 768
#define CSDIM 384
#define CZDIM 128
#define CHDIM 16
#define NHEAD 12
#define PQKN 4
#define PVN 8
#define CATDIM 2112   // 12*(128+16+4*8)
#define PROJD 1152    // 3*192 + 2*144 + 288
#define INFV 100000.0f
#define RSQRT3 0.57735026918962576f
#define PWCONST 0.23570226039551584f  // sqrt(2/(9*4))

// packed f32x2 helpers (Blackwell FFMA2 path)
#define FFMA2(d, a, b, c) asm("fma.rn.f32x2 %0, %1, %2, %3;" : "=l"(d) : "l"(a), "l"(b), "l"(c))
#define ADD2(d, a, b)     asm("add.rn.f32x2 %0, %1, %2;" : "=l"(d) : "l"(a), "l"(b))
#define PACK2(d, lo, hi)  asm("mov.b64 %0, {%1, %2};" : "=l"(d) : "f"(lo), "f"(hi))
#define UNPACK2(lo, hi, d) asm("mov.b64 {%0, %1}, %2;" : "=f"(lo), "=f"(hi) : "l"(d))

// ---------------- scratch (static device allocations) ----------------
__device__ float g_wcat[CSDIM * PROJD];
__device__ float g_proj[NRES * PROJD];
__device__ float g_qf[NRES * NHEAD * 28];
__device__ float g_kf[NRES * NHEAD * 28];
__device__ float g_gq[NRES * NHEAD];
__device__ float g_gk[NRES * NHEAD];
__device__ float g_vcat[NRES * NHEAD * 40];
__device__ float g_att[(size_t)NHEAD * NRES * NRES];  // [h][q][k]
__device__ float g_opt[NRES * NHEAD * 24];
__device__ float g_cat[NRES * CATDIM];
__device__ float g_part[3][NRES * CSDIM];             // split-K partials

// ---------------- 1: concat weights ----------------
__global__ void k_concat_w(const float* __restrict__ wq, const float* __restrict__ wk,
                           const float* __restrict__ wv, const float* __restrict__ wqp,
                           const float* __restrict__ wkp, const float* __restrict__ wvp) {
    int i = blockIdx.x * blockDim.x + threadIdx.x;
    if (i >= CSDIM * PROJD) return;
    int c = i / PROJD, col = i % PROJD;
    float v;
    if (col < 192)       v = wq[c * 192 + col];
    else if (col < 384)  v = wk[c * 192 + col - 192];
    else if (col < 576)  v = wv[c * 192 + col - 384];
    else if (col < 720)  v = wqp[c * 144 + col - 576];
    else if (col < 864)  v = wkp[c * 144 + col - 720];
    else                 v = wvp[c * 288 + col - 864];
    g_wcat[i] = v;
}

// ---------------- tiled SGEMM with register double-buffer ----------------
// C[z][M,N] = A[:, z*K : z*K+K] @ B[z*K : z*K+K, :]   (z = blockIdx.z split)
__global__ void __launch_bounds__(256) k_sgemm(const float* __restrict__ A, int lda,
                                               const float* __restrict__ B,
                                               float* __restrict__ C,
                                               int M, int N, int K) {
    A += (size_t)blockIdx.z * K;
    B += (size_t)blockIdx.z * K * N;
    C += (size_t)blockIdx.z * M * N;
    __shared__ float As[16][68];
    __shared__ float Bs[16][68];
    int tid = threadIdx.x;
    int tx = tid % 16, ty = tid / 16;
    int m0 = blockIdx.y * 64, n0 = blockIdx.x * 64;
    int ar[4], ac[4], br[4], bc[4];
#pragma unroll
    for (int u = 0; u < 4; u++) {
        int i = tid + u * 256;
        ar[u] = i / 16; ac[u] = i % 16;
        br[u] = i / 64; bc[u] = i % 64;
    }
    float pa[4], pb[4];
#pragma unroll
    for (int u = 0; u < 4; u++) {
        pa[u] = A[(size_t)(m0 + ar[u]) * lda + ac[u]];
        pb[u] = B[(size_t)br[u] * N + n0 + bc[u]];
    }
    float acc[4][4] = {};
    for (int k0 = 0; k0 < K; k0 += 16) {
        __syncthreads();
#pragma unroll
        for (int u = 0; u < 4; u++) {
            As[ac[u]][ar[u]] = pa[u];
            Bs[br[u]][bc[u]] = pb[u];
        }
        __syncthreads();
        if (k0 + 16 < K) {
#pragma unroll
            for (int u = 0; u < 4; u++) {
                pa[u] = A[(size_t)(m0 + ar[u]) * lda + k0 + 16 + ac[u]];
                pb[u] = B[(size_t)(k0 + 16 + br[u]) * N + n0 + bc[u]];
            }
        }
#pragma unroll
        for (int kk = 0; kk < 16; kk++) {
            float4 a4 = *(const float4*)&As[kk][ty * 4];
            float4 b4 = *(const float4*)&Bs[kk][tx * 4];
            float av[4] = {a4.x, a4.y, a4.z, a4.w};
            float bv[4] = {b4.x, b4.y, b4.z, b4.w};
#pragma unroll
            for (int i = 0; i < 4; i++)
#pragma unroll
                for (int j = 0; j < 4; j++) acc[i][j] += av[i] * bv[j];
        }
    }
#pragma unroll
    for (int i = 0; i < 4; i++) {
        int row = m0 + ty * 4 + i;
        float4 o;
        o.x = acc[i][0]; o.y = acc[i][1]; o.z = acc[i][2]; o.w = acc[i][3];
        *(float4*)&C[(size_t)row * N + n0 + tx * 4] = o;
    }
}

// ---------------- reduce split-K partials + bias ----------------
__global__ void k_reduce3(float* __restrict__ out, const float* __restrict__ b_out) {
    int i = blockIdx.x * 256 + threadIdx.x;
    out[i] = g_part[0][i] + g_part[1][i] + g_part[2][i] + b_out[i % CSDIM];
}

// ---------------- 3: per-residue prep ----------------
__global__ void k_prep(const float* __restrict__ bqp, const float* __restrict__ bkp,
                       const float* __restrict__ bvp, const float* __restrict__ rot,
                       const float* __restrict__ trans, const float* __restrict__ hw) {
    int n = blockIdx.x;
    int tid = threadIdx.x;  // 128 threads
    __shared__ float p[PROJD];
    __shared__ float R[9], T[3], pw[NHEAD];
    for (int i = tid; i < PROJD; i += 128) p[i] = g_proj[(size_t)n * PROJD + i];
    if (tid < 9) R[tid] = rot[n * 9 + tid];
    if (tid < 3) T[tid] = trans[n * 3 + tid];
    if (tid < NHEAD) {
        float x = hw[tid];
        float sp = (x > 20.f) ? x : log1pf(expf(x));
        pw[tid] = PWCONST * sp;
    }
    __syncthreads();
    for (int i = tid; i < 192; i += 128) {
        int h = i / 16, c = i % 16;
        g_qf[((size_t)n * NHEAD + h) * 28 + c] = p[i] * 0.25f;
        g_kf[((size_t)n * NHEAD + h) * 28 + c] = p[192 + i];
        g_vcat[((size_t)n * NHEAD + h) * 40 + c] = p[384 + i];
    }
    if (tid < 12) {
        int h = tid;
        float sq = 0.f;
        float pwh = pw[h];
        for (int pp = 0; pp < PQKN; pp++) {
            float lx = p[576 + h * 12 + 0 + pp] + bqp[h * 12 + 0 + pp];
            float ly = p[576 + h * 12 + 4 + pp] + bqp[h * 12 + 4 + pp];
            float lz = p[576 + h * 12 + 8 + pp] + bqp[h * 12 + 8 + pp];
            float gx = R[0] * lx + R[1] * ly + R[2] * lz + T[0];
            float gy = R[3] * lx + R[4] * ly + R[5] * lz + T[1];
            float gz = R[6] * lx + R[7] * ly + R[8] * lz + T[2];
            float* qo = &g_qf[((size_t)n * NHEAD + h) * 28 + 16 + pp * 3];
            qo[0] = pwh * gx; qo[1] = pwh * gy; qo[2] = pwh * gz;
            sq += gx * gx + gy * gy + gz * gz;
        }
        g_gq[n * NHEAD + h] = -0.5f * pwh * sq;
    } else if (tid < 24) {
        int h = tid - 12;
        float sq = 0.f;
        for (int pp = 0; pp < PQKN; pp++) {
            float lx = p[720 + h * 12 + 0 + pp] + bkp[h * 12 + 0 + pp];
            float ly = p[720 + h * 12 + 4 + pp] + bkp[h * 12 + 4 + pp];
            float lz = p[720 + h * 12 + 8 + pp] + bkp[h * 12 + 8 + pp];
            float gx = R[0] * lx + R[1] * ly + R[2] * lz + T[0];
            float gy = R[3] * lx + R[4] * ly + R[5] * lz + T[1];
            float gz = R[6] * lx + R[7] * ly + R[8] * lz + T[2];
            float* ko = &g_kf[((size_t)n * NHEAD + h) * 28 + 16 + pp * 3];
            ko[0] = gx; ko[1] = gy; ko[2] = gz;
            sq += gx * gx + gy * gy + gz * gz;
        }
        g_gk[n * NHEAD + h] = -0.5f * pw[h] * sq;
    } else if (tid < 36) {
        int h = tid - 24;
        for (int pp = 0; pp < PVN; pp++) {
            float lx = p[864 + h * 24 + 0 + pp] + bvp[h * 24 + 0 + pp];
            float ly = p[864 + h * 24 + 8 + pp] + bvp[h * 24 + 8 + pp];
            float lz = p[864 + h * 24 + 16 + pp] + bvp[h * 24 + 16 + pp];
            float gx = R[0] * lx + R[1] * ly + R[2] * lz + T[0];
            float gy = R[3] * lx + R[4] * ly + R[5] * lz + T[1];
            float gz = R[6] * lx + R[7] * ly + R[8] * lz + T[2];
            float* vo = &g_vcat[((size_t)n * NHEAD + h) * 40 + 16 + pp * 3];
            vo[0] = gx; vo[1] = gy; vo[2] = gz;
        }
    }
}

// ---------------- 4: pair bias (z pass #1) -> g_att[h][q][k] ----------------
// Block = (q, 256-k slice). Thread owns one k. 16-channel chunks double-buffered
// in smem: prefetch next chunk into registers (4x LDG.128, coalesced) while
// computing current chunk. One syncthreads per chunk. 12 heads = 6 f32x2 accs.
__global__ void __launch_bounds__(256) k_bbias(const float* __restrict__ z,
                                               const float* __restrict__ wb,
                                               const float* __restrict__ bb) {
    int q = blockIdx.y;
    int k0 = blockIdx.x * 256;
    int tid = threadIdx.x;
    __shared__ __align__(16) float zbuf[2][256 * 20];   // 40 KB (row stride 20 floats)
    __shared__ __align__(16) float wbs[CZDIM * NHEAD];  // 6 KB
    __shared__ float bbs[NHEAD];
    for (int i = tid; i < CZDIM * NHEAD; i += 256) wbs[i] = wb[i];
    if (tid < NHEAD) bbs[tid] = bb[tid];

    const float4* zg = (const float4*)z + ((size_t)q * NRES + k0) * 32;  // row stride 32 float4
    int srow = tid >> 2, scg = tid & 3;   // staging: row, float4-column
    float4 r[4];
#pragma unroll
    for (int u = 0; u < 4; u++)
        r[u] = zg[(size_t)(srow + u * 64) * 32 + scg];

    unsigned long long acc[6];
#pragma unroll
    for (int p = 0; p < 6; p++) acc[p] = 0ull;

    for (int cc = 0; cc < 8; cc++) {
        float* buf = zbuf[cc & 1];
#pragma unroll
        for (int u = 0; u < 4; u++)
            *(float4*)&buf[(srow + u * 64) * 20 + scg * 4] = r[u];
        __syncthreads();
        if (cc < 7) {
            int c4 = (cc + 1) * 4;
#pragma unroll
            for (int u = 0; u < 4; u++)
                r[u] = zg[(size_t)(srow + u * 64) * 32 + c4 + scg];
        }
        const float* myrow = &buf[tid * 20];
#pragma unroll
        for (int j = 0; j < 4; j++) {
            float4 z4 = *(const float4*)&myrow[j * 4];
            float zz[4] = {z4.x, z4.y, z4.z, z4.w};
            int cbase = cc * 16 + j * 4;
#pragma unroll
            for (int e = 0; e < 4; e++) {
                const unsigned long long* wp =
                    (const unsigned long long*)(wbs + (cbase + e) * NHEAD);
                unsigned long long zp;
                PACK2(zp, zz[e], zz[e]);
#pragma unroll
                for (int p = 0; p < 6; p++) FFMA2(acc[p], zp, wp[p], acc[p]);
            }
        }
    }
    int k = k0 + tid;
#pragma unroll
    for (int p = 0; p < 6; p++) {
        float lo, hi;
        UNPACK2(lo, hi, acc[p]);
        g_att[((size_t)(2 * p) * NRES + q) * NRES + k] = lo + bbs[2 * p];
        g_att[((size_t)(2 * p + 1) * NRES + q) * NRES + k] = hi + bbs[2 * p + 1];
    }
}

// ---------------- 5: logits (28-dim bilinear + additive) in-place ----------------
__global__ void __launch_bounds__(256) k_logits(const float* __restrict__ mask) {
    int h = blockIdx.z, q0 = blockIdx.y * 64, k0 = blockIdx.x * 64;
    __shared__ float Qs[28][64], Ks[28][64];
    __shared__ float gqs[64], gks[64], mqs[64], mks[64];
    int tid = threadIdx.x;
    for (int i = tid; i < 64 * 28; i += 256) {
        int r = i / 28, d = i % 28;
        Qs[d][r] = g_qf[((size_t)(q0 + r) * NHEAD + h) * 28 + d];
        Ks[d][r] = g_kf[((size_t)(k0 + r) * NHEAD + h) * 28 + d];
    }
    if (tid < 64) {
        gqs[tid] = g_gq[(q0 + tid) * NHEAD + h];
        mqs[tid] = mask[q0 + tid];
    } else if (tid < 128) {
        int r = tid - 64;
        gks[r] = g_gk[(k0 + r) * NHEAD + h];
        mks[r] = mask[k0 + r];
    }
    __syncthreads();
    int tx = tid % 16, ty = tid / 16;
    float acc[4][4] = {};
#pragma unroll
    for (int d = 0; d < 28; d++) {
        float4 a4 = *(const float4*)&Qs[d][ty * 4];
        float4 b4 = *(const float4*)&Ks[d][tx * 4];
        float av[4] = {a4.x, a4.y, a4.z, a4.w};
        float bv[4] = {b4.x, b4.y, b4.z, b4.w};
#pragma unroll
        for (int i = 0; i < 4; i++)
#pragma unroll
            for (int j = 0; j < 4; j++) acc[i][j] += av[i] * bv[j];
    }
#pragma unroll
    for (int i = 0; i < 4; i++) {
        int r = ty * 4 + i;
        size_t base = ((size_t)h * NRES + (q0 + r)) * NRES + k0 + tx * 4;
        float4 bbv = *(const float4*)&g_att[base];
        float gq = gqs[r], mq = mqs[r];
        float4 o;
        o.x = (bbv.x + acc[i][0] + gq + gks[tx * 4 + 0] + INFV * (mq * mks[tx * 4 + 0] - 1.f)) * RSQRT3;
        o.y = (bbv.y + acc[i][1] + gq + gks[tx * 4 + 1] + INFV * (mq * mks[tx * 4 + 1] - 1.f)) * RSQRT3;
        o.z = (bbv.z + acc[i][2] + gq + gks[tx * 4 + 2] + INFV * (mq * mks[tx * 4 + 2] - 1.f)) * RSQRT3;
        o.w = (bbv.w + acc[i][3] + gq + gks[tx * 4 + 3] + INFV * (mq * mks[tx * 4 + 3] - 1.f)) * RSQRT3;
        *(float4*)&g_att[base] = o;
    }
}

// ---------------- 6: softmax over k, warp per row ----------------
__global__ void __launch_bounds__(256) k_softmax() {
    int rowid = blockIdx.x * 8 + (threadIdx.x >> 5);  // flat (h*NRES + q)
    int lane = threadIdx.x & 31;
    float4* row = (float4*)(g_att + (size_t)rowid * NRES);
    float4 v[6];
#pragma unroll
    for (int i = 0; i < 6; i++) v[i] = row[lane + i * 32];
    float m = -1e30f;
#pragma unroll
    for (int i = 0; i < 6; i++)
        m = fmaxf(m, fmaxf(fmaxf(v[i].x, v[i].y), fmaxf(v[i].z, v[i].w)));
#pragma unroll
    for (int s = 16; s > 0; s >>= 1) m = fmaxf(m, __shfl_xor_sync(0xffffffffu, m, s));
    float sum = 0.f;
#pragma unroll
    for (int i = 0; i < 6; i++) {
        v[i].x = __expf(v[i].x - m); v[i].y = __expf(v[i].y - m);
        v[i].z = __expf(v[i].z - m); v[i].w = __expf(v[i].w - m);
        sum += v[i].x + v[i].y + v[i].z + v[i].w;
    }
#pragma unroll
    for (int s = 16; s > 0; s >>= 1) sum += __shfl_xor_sync(0xffffffffu, sum, s);
    float inv = 1.f / sum;
#pragma unroll
    for (int i = 0; i < 6; i++) {
        v[i].x *= inv; v[i].y *= inv; v[i].z *= inv; v[i].w *= inv;
        row[lane + i * 32] = v[i];
    }
}

// ---------------- 7: o_pair (z pass #2), packed f32x2, tree-reduce tail ----------------
__global__ void __launch_bounds__(256) k_opair(const float* __restrict__ z) {
    int q = blockIdx.x;
    int tid = threadIdx.x;
    int tx = tid % 32, ty = tid / 32;  // (32,8)
    __shared__ __align__(16) float a_s[NHEAD * NRES];  // 36 KB, reused as reduce buffer
    for (int i = tid; i < NHEAD * NRES; i += 256)
        a_s[i] = g_att[((size_t)(i / NRES) * NRES + q) * NRES + (i % NRES)];
    __syncthreads();
    unsigned long long acc2[NHEAD][2];
#pragma unroll
    for (int h = 0; h < NHEAD; h++) { acc2[h][0] = 0ull; acc2[h][1] = 0ull; }
    const ulonglong2* zr = (const ulonglong2*)(z + (size_t)q * NRES * CZDIM);
    for (int k = ty; k < NRES; k += 16) {
        ulonglong2 zv0 = zr[k * 32 + tx];
        ulonglong2 zv1 = zr[(k + 8) * 32 + tx];
#pragma unroll
        for (int h = 0; h < NHEAD; h++) {
            float ah = a_s[h * NRES + k];
            unsigned long long aa;
            PACK2(aa, ah, ah);
            FFMA2(acc2[h][0], aa, zv0.x, acc2[h][0]);
            FFMA2(acc2[h][1], aa, zv0.y, acc2[h][1]);
        }
#pragma unroll
        for (int h = 0; h < NHEAD; h++) {
            float ah = a_s[h * NRES + k + 8];
            unsigned long long aa;
            PACK2(aa, ah, ah);
            FFMA2(acc2[h][0], aa, zv1.x, acc2[h][0]);
            FFMA2(acc2[h][1], aa, zv1.y, acc2[h][1]);
        }
    }
    // tree reduce over ty (8 -> 1) in 3 rounds; slot stride 50 floats (2-way max conflicts)
    unsigned long long* red = (unsigned long long*)a_s;  // reuse; slot = idx*50 floats = idx*25 ull
    __syncthreads();
    if (ty >= 4) {
        unsigned long long* d = red + ((ty - 4) * 32 + tx) * 25;
#pragma unroll
        for (int h = 0; h < NHEAD; h++) { d[h * 2] = acc2[h][0]; d[h * 2 + 1] = acc2[h][1]; }
    }
    __syncthreads();
    if (ty < 4) {
        const unsigned long long* d = red + (ty * 32 + tx) * 25;
#pragma unroll
        for (int h = 0; h < NHEAD; h++) {
            ADD2(acc2[h][0], acc2[h][0], d[h * 2]);
            ADD2(acc2[h][1], acc2[h][1], d[h * 2 + 1]);
        }
    }
    __syncthreads();
    if (ty >= 2 && ty < 4) {
        unsigned long long* d = red + ((ty - 2) * 32 + tx) * 25;
#pragma unroll
        for (int h = 0; h < NHEAD; h++) { d[h * 2] = acc2[h][0]; d[h * 2 + 1] = acc2[h][1]; }
    }
    __syncthreads();
    if (ty < 2) {
        const unsigned long long* d = red + (ty * 32 + tx) * 25;
#pragma unroll
        for (int h = 0; h < NHEAD; h++) {
            ADD2(acc2[h][0], acc2[h][0], d[h * 2]);
            ADD2(acc2[h][1], acc2[h][1], d[h * 2 + 1]);
        }
    }
    __syncthreads();
    if (ty == 1) {
        unsigned long long* d = red + tx * 25;
#pragma unroll
        for (int h = 0; h < NHEAD; h++) { d[h * 2] = acc2[h][0]; d[h * 2 + 1] = acc2[h][1]; }
    }
    __syncthreads();
    if (ty == 0) {
        const unsigned long long* d = red + tx * 25;
        float* out = &g_cat[(size_t)q * CATDIM + 576];
#pragma unroll
        for (int h = 0; h < NHEAD; h++) {
            ADD2(acc2[h][0], acc2[h][0], d[h * 2]);
            ADD2(acc2[h][1], acc2[h][1], d[h * 2 + 1]);
            float4 o;
            UNPACK2(o.x, o.y, acc2[h][0]);
            UNPACK2(o.z, o.w, acc2[h][1]);
            *(float4*)&out[h * CZDIM + tx * 4] = o;
        }
    }
}

// ---------------- 8: o + o_pt, BQ=32, [k][q] a-tile + f32x2 ----------------
__global__ void __launch_bounds__(320) k_ov() {
    int h = blockIdx.y;
    int q0 = blockIdx.x * 32;
    __shared__ float a_t[64 * 37];   // [kk][q pad 37]
    __shared__ float v_t[64 * 40];   // [kk][c]
    int tid = threadIdx.x;           // 320
    int cg = tid % 20, qg = tid / 20;  // cg: 2-channel group, qg: 2-q group (0..15)
    unsigned long long acc[2] = {0ull, 0ull};
    for (int k0 = 0; k0 < NRES; k0 += 64) {
        if (k0) __syncthreads();
        for (int i = tid; i < 2048; i += 320) {
            int kk = i & 63, r = i >> 6;
            a_t[kk * 37 + r] = g_att[((size_t)h * NRES + q0 + r) * NRES + k0 + kk];
        }
        for (int i = tid; i < 2560; i += 320) {
            int r = i / 40, j = i % 40;
            v_t[r * 40 + j] = g_vcat[((size_t)(k0 + r) * NHEAD + h) * 40 + j];
        }
        __syncthreads();
#pragma unroll 8
        for (int kk = 0; kk < 64; kk++) {
            float a0 = a_t[kk * 37 + qg * 2];
            float a1 = a_t[kk * 37 + qg * 2 + 1];
            unsigned long long v2 = *(const unsigned long long*)&v_t[kk * 40 + cg * 2];
            unsigned long long d0, d1;
            PACK2(d0, a0, a0); FFMA2(acc[0], d0, v2, acc[0]);
            PACK2(d1, a1, a1); FFMA2(acc[1], d1, v2, acc[1]);
        }
    }
    int c = cg * 2;
#pragma unroll
    for (int r = 0; r < 2; r++) {
        int q = q0 + qg * 2 + r;
        float lo, hi;
        UNPACK2(lo, hi, acc[r]);
        if (c < 16) {
            g_cat[(size_t)q * CATDIM + h * 16 + c] = lo;
            g_cat[(size_t)q * CATDIM + h * 16 + c + 1] = hi;
        } else {
            float* o = &g_opt[((size_t)q * NHEAD + h) * 24];
            o[c - 16] = lo;
            o[c - 15] = hi;
        }
    }
}

// ---------------- 9: rigid-inverse + norms ----------------
__global__ void k_finalize(const float* __restrict__ rot, const float* __restrict__ trans) {
    int q = blockIdx.x;
    int tid = threadIdx.x;  // 96 threads
    __shared__ float R[9], T[3];
    if (tid < 9) R[tid] = rot[q * 9 + tid];
    if (tid < 3) T[tid] = trans[q * 3 + tid];
    __syncthreads();
    int h = tid / 8, pp = tid % 8;
    const float* o = &g_opt[((size_t)q * NHEAD + h) * 24 + pp * 3];
    float dx = o[0] - T[0], dy = o[1] - T[1], dz = o[2] - T[2];
    float lx = R[0] * dx + R[3] * dy + R[6] * dz;
    float ly = R[1] * dx + R[4] * dy + R[7] * dz;
    float lz = R[2] * dx + R[5] * dy + R[8] * dz;
    float nrm = sqrtf(fmaxf(lx * lx + ly * ly + lz * lz, 1e-16f));
    int col = h * 8 + pp;
    float* cr = &g_cat[(size_t)q * CATDIM];
    cr[192 + col] = lx;
    cr[288 + col] = ly;
    cr[384 + col] = lz;
    cr[480 + col] = nrm;
}

// ---------------- launcher ----------------
extern "C" void kernel_launch(void* const* d_in, const int* in_sizes, int n_in,
                              void* d_out, int out_size) {
    const float* s     = (const float*)d_in[0];
    const float* z     = (const float*)d_in[1];
    const float* mask  = (const float*)d_in[2];
    const float* rot   = (const float*)d_in[3];
    const float* trans = (const float*)d_in[4];
    const float* w_q   = (const float*)d_in[5];
    const float* w_k   = (const float*)d_in[6];
    const float* w_v   = (const float*)d_in[7];
    const float* w_qp  = (const float*)d_in[8];
    const float* b_qp  = (const float*)d_in[9];
    const float* w_kp  = (const float*)d_in[10];
    const float* b_kp  = (const float*)d_in[11];
    const float* w_vp  = (const float*)d_in[12];
    const float* b_vp  = (const float*)d_in[13];
    const float* w_b   = (const float*)d_in[14];
    const float* b_b   = (const float*)d_in[15];
    const float* hw    = (const float*)d_in[16];
    const float* w_out = (const float*)d_in[17];
    const float* b_out = (const float*)d_in[18];
    float* out = (float*)d_out;

    float *p_wcat, *p_proj, *p_cat, *p_part;
    cudaGetSymbolAddress((void**)&p_wcat, g_wcat);
    cudaGetSymbolAddress((void**)&p_proj, g_proj);
    cudaGetSymbolAddress((void**)&p_cat, g_cat);
    cudaGetSymbolAddress((void**)&p_part, g_part);

    k_concat_w<<<(CSDIM * PROJD + 255) / 256, 256>>>(w_q, w_k, w_v, w_qp, w_kp, w_vp);
    k_sgemm<<<dim3(PROJD / 64, NRES / 64, 1), 256>>>(s, CSDIM, p_wcat, p_proj,
                                                     NRES, PROJD, CSDIM);
    k_prep<<<NRES, 128>>>(b_qp, b_kp, b_vp, rot, trans, hw);
    k_bbias<<<dim3(3, NRES), 256>>>(z, w_b, b_b);
    k_logits<<<dim3(NRES / 64, NRES / 64, NHEAD), 256>>>(mask);
    k_softmax<<<NHEAD * NRES / 8, 256>>>();
    k_opair<<<NRES, 256>>>(z);
    k_ov<<<dim3(NRES / 32, NHEAD), 320>>>();
    k_finalize<<<NRES, 96>>>(rot, trans);
    // final GEMM: split-K = 3 (2112 = 3 * 704) in one 3D launch, then reduce + bias
    k_sgemm<<<dim3(CSDIM / 64, NRES / 64, 3), 256>>>(p_cat, CATDIM, w_out,
                                                     p_part, NRES, CSDIM, 704);
    k_reduce3<<<NRES * CSDIM / 256, 256>>>(out, b_out);
}

// round 15
// speedup vs baseline: 2.3495x; 1.0433x over previous
#include <cuda_runtime.h>
#include <math.h>

#define NRES 768
#define CSDIM 384
#define CZDIM 128
#define CHDIM 16
#define NHEAD 12
#define PQKN 4
#define PVN 8
#define CATDIM 2112   // 12*(128+16+4*8)
#define PROJD 1152    // 3*192 + 2*144 + 288
#define INFV 100000.0f
#define RSQRT3 0.57735026918962576f
#define PWCONST 0.23570226039551584f  // sqrt(2/(9*4))

// packed f32x2 helpers (Blackwell FFMA2 path)
#define FFMA2(d, a, b, c) asm("fma.rn.f32x2 %0, %1, %2, %3;" : "=l"(d) : "l"(a), "l"(b), "l"(c))
#define ADD2(d, a, b)     asm("add.rn.f32x2 %0, %1, %2;" : "=l"(d) : "l"(a), "l"(b))
#define PACK2(d, lo, hi)  asm("mov.b64 %0, {%1, %2};" : "=l"(d) : "f"(lo), "f"(hi))
#define UNPACK2(lo, hi, d) asm("mov.b64 {%0, %1}, %2;" : "=f"(lo), "=f"(hi) : "l"(d))

// ---------------- scratch (static device allocations) ----------------
__device__ float g_wcat[CSDIM * PROJD];
__device__ float g_proj[NRES * PROJD];
__device__ float g_qf[NRES * NHEAD * 28];
__device__ float g_kf[NRES * NHEAD * 28];
__device__ float g_gq[NRES * NHEAD];
__device__ float g_gk[NRES * NHEAD];
__device__ float g_vcat[NRES * NHEAD * 40];
__device__ float g_att[(size_t)NHEAD * NRES * NRES];  // [h][q][k]
__device__ float g_opt[NRES * NHEAD * 24];
__device__ float g_cat[NRES * CATDIM];
__device__ float g_part[3][NRES * CSDIM];             // split-K partials

// ---------------- 1: concat weights ----------------
__global__ void k_concat_w(const float* __restrict__ wq, const float* __restrict__ wk,
                           const float* __restrict__ wv, const float* __restrict__ wqp,
                           const float* __restrict__ wkp, const float* __restrict__ wvp) {
    int i = blockIdx.x * blockDim.x + threadIdx.x;
    if (i >= CSDIM * PROJD) return;
    int c = i / PROJD, col = i % PROJD;
    float v;
    if (col < 192)       v = wq[c * 192 + col];
    else if (col < 384)  v = wk[c * 192 + col - 192];
    else if (col < 576)  v = wv[c * 192 + col - 384];
    else if (col < 720)  v = wqp[c * 144 + col - 576];
    else if (col < 864)  v = wkp[c * 144 + col - 720];
    else                 v = wvp[c * 288 + col - 864];
    g_wcat[i] = v;
}

// ---------------- tiled SGEMM with register double-buffer ----------------
// C[z][M,N] = A[:, z*K : z*K+K] @ B[z*K : z*K+K, :]   (z = blockIdx.z split)
__global__ void __launch_bounds__(256) k_sgemm(const float* __restrict__ A, int lda,
                                               const float* __restrict__ B,
                                               float* __restrict__ C,
                                               int M, int N, int K) {
    A += (size_t)blockIdx.z * K;
    B += (size_t)blockIdx.z * K * N;
    C += (size_t)blockIdx.z * M * N;
    __shared__ float As[16][68];
    __shared__ float Bs[16][68];
    int tid = threadIdx.x;
    int tx = tid % 16, ty = tid / 16;
    int m0 = blockIdx.y * 64, n0 = blockIdx.x * 64;
    int ar[4], ac[4], br[4], bc[4];
#pragma unroll
    for (int u = 0; u < 4; u++) {
        int i = tid + u * 256;
        ar[u] = i / 16; ac[u] = i % 16;
        br[u] = i / 64; bc[u] = i % 64;
    }
    float pa[4], pb[4];
#pragma unroll
    for (int u = 0; u < 4; u++) {
        pa[u] = A[(size_t)(m0 + ar[u]) * lda + ac[u]];
        pb[u] = B[(size_t)br[u] * N + n0 + bc[u]];
    }
    float acc[4][4] = {};
    for (int k0 = 0; k0 < K; k0 += 16) {
        __syncthreads();
#pragma unroll
        for (int u = 0; u < 4; u++) {
            As[ac[u]][ar[u]] = pa[u];
            Bs[br[u]][bc[u]] = pb[u];
        }
        __syncthreads();
        if (k0 + 16 < K) {
#pragma unroll
            for (int u = 0; u < 4; u++) {
                pa[u] = A[(size_t)(m0 + ar[u]) * lda + k0 + 16 + ac[u]];
                pb[u] = B[(size_t)(k0 + 16 + br[u]) * N + n0 + bc[u]];
            }
        }
#pragma unroll
        for (int kk = 0; kk < 16; kk++) {
            float4 a4 = *(const float4*)&As[kk][ty * 4];
            float4 b4 = *(const float4*)&Bs[kk][tx * 4];
            float av[4] = {a4.x, a4.y, a4.z, a4.w};
            float bv[4] = {b4.x, b4.y, b4.z, b4.w};
#pragma unroll
            for (int i = 0; i < 4; i++)
#pragma unroll
                for (int j = 0; j < 4; j++) acc[i][j] += av[i] * bv[j];
        }
    }
#pragma unroll
    for (int i = 0; i < 4; i++) {
        int row = m0 + ty * 4 + i;
        float4 o;
        o.x = acc[i][0]; o.y = acc[i][1]; o.z = acc[i][2]; o.w = acc[i][3];
        *(float4*)&C[(size_t)row * N + n0 + tx * 4] = o;
    }
}

// ---------------- reduce split-K partials + bias ----------------
__global__ void k_reduce3(float* __restrict__ out, const float* __restrict__ b_out) {
    int i = blockIdx.x * 256 + threadIdx.x;
    out[i] = g_part[0][i] + g_part[1][i] + g_part[2][i] + b_out[i % CSDIM];
}

// ---------------- 3: per-residue prep ----------------
__global__ void k_prep(const float* __restrict__ bqp, const float* __restrict__ bkp,
                       const float* __restrict__ bvp, const float* __restrict__ rot,
                       const float* __restrict__ trans, const float* __restrict__ hw) {
    int n = blockIdx.x;
    int tid = threadIdx.x;  // 128 threads
    __shared__ float p[PROJD];
    __shared__ float R[9], T[3], pw[NHEAD];
    for (int i = tid; i < PROJD; i += 128) p[i] = g_proj[(size_t)n * PROJD + i];
    if (tid < 9) R[tid] = rot[n * 9 + tid];
    if (tid < 3) T[tid] = trans[n * 3 + tid];
    if (tid < NHEAD) {
        float x = hw[tid];
        float sp = (x > 20.f) ? x : log1pf(expf(x));
        pw[tid] = PWCONST * sp;
    }
    __syncthreads();
    for (int i = tid; i < 192; i += 128) {
        int h = i / 16, c = i % 16;
        g_qf[((size_t)n * NHEAD + h) * 28 + c] = p[i] * 0.25f;
        g_kf[((size_t)n * NHEAD + h) * 28 + c] = p[192 + i];
        g_vcat[((size_t)n * NHEAD + h) * 40 + c] = p[384 + i];
    }
    if (tid < 12) {
        int h = tid;
        float sq = 0.f;
        float pwh = pw[h];
        for (int pp = 0; pp < PQKN; pp++) {
            float lx = p[576 + h * 12 + 0 + pp] + bqp[h * 12 + 0 + pp];
            float ly = p[576 + h * 12 + 4 + pp] + bqp[h * 12 + 4 + pp];
            float lz = p[576 + h * 12 + 8 + pp] + bqp[h * 12 + 8 + pp];
            float gx = R[0] * lx + R[1] * ly + R[2] * lz + T[0];
            float gy = R[3] * lx + R[4] * ly + R[5] * lz + T[1];
            float gz = R[6] * lx + R[7] * ly + R[8] * lz + T[2];
            float* qo = &g_qf[((size_t)n * NHEAD + h) * 28 + 16 + pp * 3];
            qo[0] = pwh * gx; qo[1] = pwh * gy; qo[2] = pwh * gz;
            sq += gx * gx + gy * gy + gz * gz;
        }
        g_gq[n * NHEAD + h] = -0.5f * pwh * sq;
    } else if (tid < 24) {
        int h = tid - 12;
        float sq = 0.f;
        for (int pp = 0; pp < PQKN; pp++) {
            float lx = p[720 + h * 12 + 0 + pp] + bkp[h * 12 + 0 + pp];
            float ly = p[720 + h * 12 + 4 + pp] + bkp[h * 12 + 4 + pp];
            float lz = p[720 + h * 12 + 8 + pp] + bkp[h * 12 + 8 + pp];
            float gx = R[0] * lx + R[1] * ly + R[2] * lz + T[0];
            float gy = R[3] * lx + R[4] * ly + R[5] * lz + T[1];
            float gz = R[6] * lx + R[7] * ly + R[8] * lz + T[2];
            float* ko = &g_kf[((size_t)n * NHEAD + h) * 28 + 16 + pp * 3];
            ko[0] = gx; ko[1] = gy; ko[2] = gz;
            sq += gx * gx + gy * gy + gz * gz;
        }
        g_gk[n * NHEAD + h] = -0.5f * pw[h] * sq;
    } else if (tid < 36) {
        int h = tid - 24;
        for (int pp = 0; pp < PVN; pp++) {
            float lx = p[864 + h * 24 + 0 + pp] + bvp[h * 24 + 0 + pp];
            float ly = p[864 + h * 24 + 8 + pp] + bvp[h * 24 + 8 + pp];
            float lz = p[864 + h * 24 + 16 + pp] + bvp[h * 24 + 16 + pp];
            float gx = R[0] * lx + R[1] * ly + R[2] * lz + T[0];
            float gy = R[3] * lx + R[4] * ly + R[5] * lz + T[1];
            float gz = R[6] * lx + R[7] * ly + R[8] * lz + T[2];
            float* vo = &g_vcat[((size_t)n * NHEAD + h) * 40 + 16 + pp * 3];
            vo[0] = gx; vo[1] = gy; vo[2] = gz;
        }
    }
}

// ---------------- 4: pair bias (z pass #1) -> g_att[h][q][k] ----------------
// v6: block = (q, 256-k slice), 128 threads, 2 k per thread (tid, tid+128).
// 4 chunks of 32 channels: each 128B z line staged exactly once, fully consumed.
// Row stride 36 floats (16B-aligned float4 accesses, conflict-free banks:
// 4*tid mod 32 covers all banks per 8-lane phase). Compute reads LDS.128
// (4 channels/load). w loaded as ull pairs, amortized over 2 k.
__global__ void __launch_bounds__(128) k_bbias(const float* __restrict__ z,
                                               const float* __restrict__ wb,
                                               const float* __restrict__ bb) {
    int q = blockIdx.y;
    int k0 = blockIdx.x * 256;
    int tid = threadIdx.x;
    __shared__ __align__(16) float zbuf[256 * 36];      // 36.9 KB
    __shared__ __align__(16) float wbs[CZDIM * NHEAD];  // 6 KB
    __shared__ float bbs[NHEAD];
    for (int i = tid; i < CZDIM * NHEAD; i += 128) wbs[i] = wb[i];
    if (tid < NHEAD) bbs[tid] = bb[tid];

    const float4* zg4 = (const float4*)z + ((size_t)q * NRES + k0) * 32;  // row stride 32 float4

    unsigned long long acc[2][6];
#pragma unroll
    for (int kc = 0; kc < 2; kc++)
#pragma unroll
        for (int p = 0; p < 6; p++) acc[kc][p] = 0ull;

    for (int cc = 0; cc < 4; cc++) {
        __syncthreads();   // zbuf reuse guard (and covers wbs on first iter)
        // stage 256 rows x 32 channels: thread does 16 float4; warp instruction
        // covers 4 rows x 128B contiguous = 4 fully-consumed lines.
#pragma unroll
        for (int i = 0; i < 16; i++) {
            int f = tid + i * 128;
            int row = f >> 3, c4 = f & 7;
            *(float4*)&zbuf[row * 36 + c4 * 4] = zg4[(size_t)row * 32 + cc * 8 + c4];
        }
        __syncthreads();
#pragma unroll
        for (int ch4 = 0; ch4 < 8; ch4++) {
            float4 za = *(const float4*)&zbuf[tid * 36 + ch4 * 4];
            float4 zb = *(const float4*)&zbuf[(tid + 128) * 36 + ch4 * 4];
            float z0v[4] = {za.x, za.y, za.z, za.w};
            float z1v[4] = {zb.x, zb.y, zb.z, zb.w};
            int cbase = cc * 32 + ch4 * 4;
#pragma unroll
            for (int e = 0; e < 4; e++) {
                const unsigned long long* wp =
                    (const unsigned long long*)(wbs + (cbase + e) * NHEAD);
                unsigned long long w0 = wp[0], w1 = wp[1], w2 = wp[2],
                                   w3 = wp[3], w4 = wp[4], w5 = wp[5];
                unsigned long long zp0, zp1;
                PACK2(zp0, z0v[e], z0v[e]);
                PACK2(zp1, z1v[e], z1v[e]);
                FFMA2(acc[0][0], zp0, w0, acc[0][0]);
                FFMA2(acc[0][1], zp0, w1, acc[0][1]);
                FFMA2(acc[0][2], zp0, w2, acc[0][2]);
                FFMA2(acc[0][3], zp0, w3, acc[0][3]);
                FFMA2(acc[0][4], zp0, w4, acc[0][4]);
                FFMA2(acc[0][5], zp0, w5, acc[0][5]);
                FFMA2(acc[1][0], zp1, w0, acc[1][0]);
                FFMA2(acc[1][1], zp1, w1, acc[1][1]);
                FFMA2(acc[1][2], zp1, w2, acc[1][2]);
                FFMA2(acc[1][3], zp1, w3, acc[1][3]);
                FFMA2(acc[1][4], zp1, w4, acc[1][4]);
                FFMA2(acc[1][5], zp1, w5, acc[1][5]);
            }
        }
    }
#pragma unroll
    for (int kc = 0; kc < 2; kc++) {
        int k = k0 + kc * 128 + tid;
#pragma unroll
        for (int p = 0; p < 6; p++) {
            float lo, hi;
            UNPACK2(lo, hi, acc[kc][p]);
            g_att[((size_t)(2 * p) * NRES + q) * NRES + k] = lo + bbs[2 * p];
            g_att[((size_t)(2 * p + 1) * NRES + q) * NRES + k] = hi + bbs[2 * p + 1];
        }
    }
}

// ---------------- 5: logits (28-dim bilinear + additive) in-place ----------------
__global__ void __launch_bounds__(256) k_logits(const float* __restrict__ mask) {
    int h = blockIdx.z, q0 = blockIdx.y * 64, k0 = blockIdx.x * 64;
    __shared__ float Qs[28][64], Ks[28][64];
    __shared__ float gqs[64], gks[64], mqs[64], mks[64];
    int tid = threadIdx.x;
    for (int i = tid; i < 64 * 28; i += 256) {
        int r = i / 28, d = i % 28;
        Qs[d][r] = g_qf[((size_t)(q0 + r) * NHEAD + h) * 28 + d];
        Ks[d][r] = g_kf[((size_t)(k0 + r) * NHEAD + h) * 28 + d];
    }
    if (tid < 64) {
        gqs[tid] = g_gq[(q0 + tid) * NHEAD + h];
        mqs[tid] = mask[q0 + tid];
    } else if (tid < 128) {
        int r = tid - 64;
        gks[r] = g_gk[(k0 + r) * NHEAD + h];
        mks[r] = mask[k0 + r];
    }
    __syncthreads();
    int tx = tid % 16, ty = tid / 16;
    float acc[4][4] = {};
#pragma unroll
    for (int d = 0; d < 28; d++) {
        float4 a4 = *(const float4*)&Qs[d][ty * 4];
        float4 b4 = *(const float4*)&Ks[d][tx * 4];
        float av[4] = {a4.x, a4.y, a4.z, a4.w};
        float bv[4] = {b4.x, b4.y, b4.z, b4.w};
#pragma unroll
        for (int i = 0; i < 4; i++)
#pragma unroll
            for (int j = 0; j < 4; j++) acc[i][j] += av[i] * bv[j];
    }
#pragma unroll
    for (int i = 0; i < 4; i++) {
        int r = ty * 4 + i;
        size_t base = ((size_t)h * NRES + (q0 + r)) * NRES + k0 + tx * 4;
        float4 bbv = *(const float4*)&g_att[base];
        float gq = gqs[r], mq = mqs[r];
        float4 o;
        o.x = (bbv.x + acc[i][0] + gq + gks[tx * 4 + 0] + INFV * (mq * mks[tx * 4 + 0] - 1.f)) * RSQRT3;
        o.y = (bbv.y + acc[i][1] + gq + gks[tx * 4 + 1] + INFV * (mq * mks[tx * 4 + 1] - 1.f)) * RSQRT3;
        o.z = (bbv.z + acc[i][2] + gq + gks[tx * 4 + 2] + INFV * (mq * mks[tx * 4 + 2] - 1.f)) * RSQRT3;
        o.w = (bbv.w + acc[i][3] + gq + gks[tx * 4 + 3] + INFV * (mq * mks[tx * 4 + 3] - 1.f)) * RSQRT3;
        *(float4*)&g_att[base] = o;
    }
}

// ---------------- 6: softmax over k, warp per row ----------------
__global__ void __launch_bounds__(256) k_softmax() {
    int rowid = blockIdx.x * 8 + (threadIdx.x >> 5);  // flat (h*NRES + q)
    int lane = threadIdx.x & 31;
    float4* row = (float4*)(g_att + (size_t)rowid * NRES);
    float4 v[6];
#pragma unroll
    for (int i = 0; i < 6; i++) v[i] = row[lane + i * 32];
    float m = -1e30f;
#pragma unroll
    for (int i = 0; i < 6; i++)
        m = fmaxf(m, fmaxf(fmaxf(v[i].x, v[i].y), fmaxf(v[i].z, v[i].w)));
#pragma unroll
    for (int s = 16; s > 0; s >>= 1) m = fmaxf(m, __shfl_xor_sync(0xffffffffu, m, s));
    float sum = 0.f;
#pragma unroll
    for (int i = 0; i < 6; i++) {
        v[i].x = __expf(v[i].x - m); v[i].y = __expf(v[i].y - m);
        v[i].z = __expf(v[i].z - m); v[i].w = __expf(v[i].w - m);
        sum += v[i].x + v[i].y + v[i].z + v[i].w;
    }
#pragma unroll
    for (int s = 16; s > 0; s >>= 1) sum += __shfl_xor_sync(0xffffffffu, sum, s);
    float inv = 1.f / sum;
#pragma unroll
    for (int i = 0; i < 6; i++) {
        v[i].x *= inv; v[i].y *= inv; v[i].z *= inv; v[i].w *= inv;
        row[lane + i * 32] = v[i];
    }
}

// ---------------- 7: o_pair (z pass #2), packed f32x2, tree-reduce tail ----------------
__global__ void __launch_bounds__(256) k_opair(const float* __restrict__ z) {
    int q = blockIdx.x;
    int tid = threadIdx.x;
    int tx = tid % 32, ty = tid / 32;  // (32,8)
    __shared__ __align__(16) float a_s[NHEAD * NRES];  // 36 KB, reused as reduce buffer
    for (int i = tid; i < NHEAD * NRES; i += 256)
        a_s[i] = g_att[((size_t)(i / NRES) * NRES + q) * NRES + (i % NRES)];
    __syncthreads();
    unsigned long long acc2[NHEAD][2];
#pragma unroll
    for (int h = 0; h < NHEAD; h++) { acc2[h][0] = 0ull; acc2[h][1] = 0ull; }
    const ulonglong2* zr = (const ulonglong2*)(z + (size_t)q * NRES * CZDIM);
    for (int k = ty; k < NRES; k += 16) {
        ulonglong2 zv0 = zr[k * 32 + tx];
        ulonglong2 zv1 = zr[(k + 8) * 32 + tx];
#pragma unroll
        for (int h = 0; h < NHEAD; h++) {
            float ah = a_s[h * NRES + k];
            unsigned long long aa;
            PACK2(aa, ah, ah);
            FFMA2(acc2[h][0], aa, zv0.x, acc2[h][0]);
            FFMA2(acc2[h][1], aa, zv0.y, acc2[h][1]);
        }
#pragma unroll
        for (int h = 0; h < NHEAD; h++) {
            float ah = a_s[h * NRES + k + 8];
            unsigned long long aa;
            PACK2(aa, ah, ah);
            FFMA2(acc2[h][0], aa, zv1.x, acc2[h][0]);
            FFMA2(acc2[h][1], aa, zv1.y, acc2[h][1]);
        }
    }
    // tree reduce over ty (8 -> 1) in 3 rounds; slot stride 50 floats (2-way max conflicts)
    unsigned long long* red = (unsigned long long*)a_s;  // reuse; slot = idx*50 floats = idx*25 ull
    __syncthreads();
    if (ty >= 4) {
        unsigned long long* d = red + ((ty - 4) * 32 + tx) * 25;
#pragma unroll
        for (int h = 0; h < NHEAD; h++) { d[h * 2] = acc2[h][0]; d[h * 2 + 1] = acc2[h][1]; }
    }
    __syncthreads();
    if (ty < 4) {
        const unsigned long long* d = red + (ty * 32 + tx) * 25;
#pragma unroll
        for (int h = 0; h < NHEAD; h++) {
            ADD2(acc2[h][0], acc2[h][0], d[h * 2]);
            ADD2(acc2[h][1], acc2[h][1], d[h * 2 + 1]);
        }
    }
    __syncthreads();
    if (ty >= 2 && ty < 4) {
        unsigned long long* d = red + ((ty - 2) * 32 + tx) * 25;
#pragma unroll
        for (int h = 0; h < NHEAD; h++) { d[h * 2] = acc2[h][0]; d[h * 2 + 1] = acc2[h][1]; }
    }
    __syncthreads();
    if (ty < 2) {
        const unsigned long long* d = red + (ty * 32 + tx) * 25;
#pragma unroll
        for (int h = 0; h < NHEAD; h++) {
            ADD2(acc2[h][0], acc2[h][0], d[h * 2]);
            ADD2(acc2[h][1], acc2[h][1], d[h * 2 + 1]);
        }
    }
    __syncthreads();
    if (ty == 1) {
        unsigned long long* d = red + tx * 25;
#pragma unroll
        for (int h = 0; h < NHEAD; h++) { d[h * 2] = acc2[h][0]; d[h * 2 + 1] = acc2[h][1]; }
    }
    __syncthreads();
    if (ty == 0) {
        const unsigned long long* d = red + tx * 25;
        float* out = &g_cat[(size_t)q * CATDIM + 576];
#pragma unroll
        for (int h = 0; h < NHEAD; h++) {
            ADD2(acc2[h][0], acc2[h][0], d[h * 2]);
            ADD2(acc2[h][1], acc2[h][1], d[h * 2 + 1]);
            float4 o;
            UNPACK2(o.x, o.y, acc2[h][0]);
            UNPACK2(o.z, o.w, acc2[h][1]);
            *(float4*)&out[h * CZDIM + tx * 4] = o;
        }
    }
}

// ---------------- 8: o + o_pt, BQ=32, [k][q] a-tile + f32x2 ----------------
__global__ void __launch_bounds__(320) k_ov() {
    int h = blockIdx.y;
    int q0 = blockIdx.x * 32;
    __shared__ float a_t[64 * 37];   // [kk][q pad 37]
    __shared__ float v_t[64 * 40];   // [kk][c]
    int tid = threadIdx.x;           // 320
    int cg = tid % 20, qg = tid / 20;  // cg: 2-channel group, qg: 2-q group (0..15)
    unsigned long long acc[2] = {0ull, 0ull};
    for (int k0 = 0; k0 < NRES; k0 += 64) {
        if (k0) __syncthreads();
        for (int i = tid; i < 2048; i += 320) {
            int kk = i & 63, r = i >> 6;
            a_t[kk * 37 + r] = g_att[((size_t)h * NRES + q0 + r) * NRES + k0 + kk];
        }
        for (int i = tid; i < 2560; i += 320) {
            int r = i / 40, j = i % 40;
            v_t[r * 40 + j] = g_vcat[((size_t)(k0 + r) * NHEAD + h) * 40 + j];
        }
        __syncthreads();
#pragma unroll 8
        for (int kk = 0; kk < 64; kk++) {
            float a0 = a_t[kk * 37 + qg * 2];
            float a1 = a_t[kk * 37 + qg * 2 + 1];
            unsigned long long v2 = *(const unsigned long long*)&v_t[kk * 40 + cg * 2];
            unsigned long long d0, d1;
            PACK2(d0, a0, a0); FFMA2(acc[0], d0, v2, acc[0]);
            PACK2(d1, a1, a1); FFMA2(acc[1], d1, v2, acc[1]);
        }
    }
    int c = cg * 2;
#pragma unroll
    for (int r = 0; r < 2; r++) {
        int q = q0 + qg * 2 + r;
        float lo, hi;
        UNPACK2(lo, hi, acc[r]);
        if (c < 16) {
            g_cat[(size_t)q * CATDIM + h * 16 + c] = lo;
            g_cat[(size_t)q * CATDIM + h * 16 + c + 1] = hi;
        } else {
            float* o = &g_opt[((size_t)q * NHEAD + h) * 24];
            o[c - 16] = lo;
            o[c - 15] = hi;
        }
    }
}

// ---------------- 9: rigid-inverse + norms ----------------
__global__ void k_finalize(const float* __restrict__ rot, const float* __restrict__ trans) {
    int q = blockIdx.x;
    int tid = threadIdx.x;  // 96 threads
    __shared__ float R[9], T[3];
    if (tid < 9) R[tid] = rot[q * 9 + tid];
    if (tid < 3) T[tid] = trans[q * 3 + tid];
    __syncthreads();
    int h = tid / 8, pp = tid % 8;
    const float* o = &g_opt[((size_t)q * NHEAD + h) * 24 + pp * 3];
    float dx = o[0] - T[0], dy = o[1] - T[1], dz = o[2] - T[2];
    float lx = R[0] * dx + R[3] * dy + R[6] * dz;
    float ly = R[1] * dx + R[4] * dy + R[7] * dz;
    float lz = R[2] * dx + R[5] * dy + R[8] * dz;
    float nrm = sqrtf(fmaxf(lx * lx + ly * ly + lz * lz, 1e-16f));
    int col = h * 8 + pp;
    float* cr = &g_cat[(size_t)q * CATDIM];
    cr[192 + col] = lx;
    cr[288 + col] = ly;
    cr[384 + col] = lz;
    cr[480 + col] = nrm;
}

// ---------------- launcher ----------------
extern "C" void kernel_launch(void* const* d_in, const int* in_sizes, int n_in,
                              void* d_out, int out_size) {
    const float* s     = (const float*)d_in[0];
    const float* z     = (const float*)d_in[1];
    const float* mask  = (const float*)d_in[2];
    const float* rot   = (const float*)d_in[3];
    const float* trans = (const float*)d_in[4];
    const float* w_q   = (const float*)d_in[5];
    const float* w_k   = (const float*)d_in[6];
    const float* w_v   = (const float*)d_in[7];
    const float* w_qp  = (const float*)d_in[8];
    const float* b_qp  = (const float*)d_in[9];
    const float* w_kp  = (const float*)d_in[10];
    const float* b_kp  = (const float*)d_in[11];
    const float* w_vp  = (const float*)d_in[12];
    const float* b_vp  = (const float*)d_in[13];
    const float* w_b   = (const float*)d_in[14];
    const float* b_b   = (const float*)d_in[15];
    const float* hw    = (const float*)d_in[16];
    const float* w_out = (const float*)d_in[17];
    const float* b_out = (const float*)d_in[18];
    float* out = (float*)d_out;

    float *p_wcat, *p_proj, *p_cat, *p_part;
    cudaGetSymbolAddress((void**)&p_wcat, g_wcat);
    cudaGetSymbolAddress((void**)&p_proj, g_proj);
    cudaGetSymbolAddress((void**)&p_cat, g_cat);
    cudaGetSymbolAddress((void**)&p_part, g_part);

    k_concat_w<<<(CSDIM * PROJD + 255) / 256, 256>>>(w_q, w_k, w_v, w_qp, w_kp, w_vp);
    k_sgemm<<<dim3(PROJD / 64, NRES / 64, 1), 256>>>(s, CSDIM, p_wcat, p_proj,
                                                     NRES, PROJD, CSDIM);
    k_prep<<<NRES, 128>>>(b_qp, b_kp, b_vp, rot, trans, hw);
    k_bbias<<<dim3(3, NRES), 128>>>(z, w_b, b_b);
    k_logits<<<dim3(NRES / 64, NRES / 64, NHEAD), 256>>>(mask);
    k_softmax<<<NHEAD * NRES / 8, 256>>>();
    k_opair<<<NRES, 256>>>(z);
    k_ov<<<dim3(NRES / 32, NHEAD), 320>>>();
    k_finalize<<<NRES, 96>>>(rot, trans);
    // final GEMM: split-K = 3 (2112 = 3 * 704) in one 3D launch, then reduce + bias
    k_sgemm<<<dim3(CSDIM / 64, NRES / 64, 3), 256>>>(p_cat, CATDIM, w_out,
                                                     p_part, NRES, CSDIM, 704);
    k_reduce3<<<NRES * CSDIM / 256, 256>>>(out, b_out);
}

// round 17
// speedup vs baseline: 2.3720x; 1.0096x over previous
#include <cuda_runtime.h>
#include <math.h>

#define NRES 768
#define CSDIM 384
#define CZDIM 128
#define CHDIM 16
#define NHEAD 12
#define PQKN 4
#define PVN 8
#define CATDIM 2112   // 12*(128+16+4*8)
#define PROJD 1152    // 3*192 + 2*144 + 288
#define INFV 100000.0f
#define RSQRT3 0.57735026918962576f
#define PWCONST 0.23570226039551584f  // sqrt(2/(9*4))

// packed f32x2 helpers (Blackwell FFMA2 path)
#define FFMA2(d, a, b, c) asm("fma.rn.f32x2 %0, %1, %2, %3;" : "=l"(d) : "l"(a), "l"(b), "l"(c))
#define ADD2(d, a, b)     asm("add.rn.f32x2 %0, %1, %2;" : "=l"(d) : "l"(a), "l"(b))
#define PACK2(d, lo, hi)  asm("mov.b64 %0, {%1, %2};" : "=l"(d) : "f"(lo), "f"(hi))
#define UNPACK2(lo, hi, d) asm("mov.b64 {%0, %1}, %2;" : "=f"(lo), "=f"(hi) : "l"(d))

// ---------------- scratch (static device allocations) ----------------
__device__ float g_wcat[CSDIM * PROJD];
__device__ float g_proj[NRES * PROJD];
__device__ float g_qf[NRES * NHEAD * 28];
__device__ float g_kf[NRES * NHEAD * 28];
__device__ float g_gq[NRES * NHEAD];
__device__ float g_gk[NRES * NHEAD];
__device__ float g_vcat[NRES * NHEAD * 40];
__device__ float g_att[(size_t)NHEAD * NRES * NRES];  // [h][q][k]
__device__ float g_opt[NRES * NHEAD * 24];
__device__ float g_cat[NRES * CATDIM];
__device__ float g_part[3][NRES * CSDIM];             // split-K partials

// ---------------- 1: concat weights ----------------
__global__ void k_concat_w(const float* __restrict__ wq, const float* __restrict__ wk,
                           const float* __restrict__ wv, const float* __restrict__ wqp,
                           const float* __restrict__ wkp, const float* __restrict__ wvp) {
    int i = blockIdx.x * blockDim.x + threadIdx.x;
    if (i >= CSDIM * PROJD) return;
    int c = i / PROJD, col = i % PROJD;
    float v;
    if (col < 192)       v = wq[c * 192 + col];
    else if (col < 384)  v = wk[c * 192 + col - 192];
    else if (col < 576)  v = wv[c * 192 + col - 384];
    else if (col < 720)  v = wqp[c * 144 + col - 576];
    else if (col < 864)  v = wkp[c * 144 + col - 720];
    else                 v = wvp[c * 288 + col - 864];
    g_wcat[i] = v;
}

// ---------------- tiled SGEMM, register double-buffer + f32x2 inner ----------------
// C[z][M,N] = A[:, z*K : z*K+K] @ B[z*K : z*K+K, :]   (z = blockIdx.z split)
__global__ void __launch_bounds__(256) k_sgemm(const float* __restrict__ A, int lda,
                                               const float* __restrict__ B,
                                               float* __restrict__ C,
                                               int M, int N, int K) {
    A += (size_t)blockIdx.z * K;
    B += (size_t)blockIdx.z * K * N;
    C += (size_t)blockIdx.z * M * N;
    __shared__ __align__(16) float As[16][68];
    __shared__ __align__(16) float Bs[16][68];
    int tid = threadIdx.x;
    int tx = tid % 16, ty = tid / 16;
    int m0 = blockIdx.y * 64, n0 = blockIdx.x * 64;
    int ar[4], ac[4], br[4], bc[4];
#pragma unroll
    for (int u = 0; u < 4; u++) {
        int i = tid + u * 256;
        ar[u] = i / 16; ac[u] = i % 16;
        br[u] = i / 64; bc[u] = i % 64;
    }
    float pa[4], pb[4];
#pragma unroll
    for (int u = 0; u < 4; u++) {
        pa[u] = A[(size_t)(m0 + ar[u]) * lda + ac[u]];
        pb[u] = B[(size_t)br[u] * N + n0 + bc[u]];
    }
    unsigned long long acc2[4][2];
#pragma unroll
    for (int i = 0; i < 4; i++) { acc2[i][0] = 0ull; acc2[i][1] = 0ull; }
    for (int k0 = 0; k0 < K; k0 += 16) {
        __syncthreads();
#pragma unroll
        for (int u = 0; u < 4; u++) {
            As[ac[u]][ar[u]] = pa[u];
            Bs[br[u]][bc[u]] = pb[u];
        }
        __syncthreads();
        if (k0 + 16 < K) {
#pragma unroll
            for (int u = 0; u < 4; u++) {
                pa[u] = A[(size_t)(m0 + ar[u]) * lda + k0 + 16 + ac[u]];
                pb[u] = B[(size_t)(k0 + 16 + br[u]) * N + n0 + bc[u]];
            }
        }
#pragma unroll
        for (int kk = 0; kk < 16; kk++) {
            float4 a4 = *(const float4*)&As[kk][ty * 4];
            const unsigned long long* bp = (const unsigned long long*)&Bs[kk][tx * 4];
            unsigned long long b0 = bp[0], b1 = bp[1];
            float av[4] = {a4.x, a4.y, a4.z, a4.w};
#pragma unroll
            for (int i = 0; i < 4; i++) {
                unsigned long long ap;
                PACK2(ap, av[i], av[i]);
                FFMA2(acc2[i][0], ap, b0, acc2[i][0]);
                FFMA2(acc2[i][1], ap, b1, acc2[i][1]);
            }
        }
    }
#pragma unroll
    for (int i = 0; i < 4; i++) {
        int row = m0 + ty * 4 + i;
        float4 o;
        UNPACK2(o.x, o.y, acc2[i][0]);
        UNPACK2(o.z, o.w, acc2[i][1]);
        *(float4*)&C[(size_t)row * N + n0 + tx * 4] = o;
    }
}

// ---------------- reduce split-K partials + bias ----------------
__global__ void k_reduce3(float* __restrict__ out, const float* __restrict__ b_out) {
    int i = blockIdx.x * 256 + threadIdx.x;
    out[i] = g_part[0][i] + g_part[1][i] + g_part[2][i] + b_out[i % CSDIM];
}

// ---------------- 3: per-residue prep ----------------
__global__ void k_prep(const float* __restrict__ bqp, const float* __restrict__ bkp,
                       const float* __restrict__ bvp, const float* __restrict__ rot,
                       const float* __restrict__ trans, const float* __restrict__ hw) {
    int n = blockIdx.x;
    int tid = threadIdx.x;  // 128 threads
    __shared__ float p[PROJD];
    __shared__ float R[9], T[3], pw[NHEAD];
    for (int i = tid; i < PROJD; i += 128) p[i] = g_proj[(size_t)n * PROJD + i];
    if (tid < 9) R[tid] = rot[n * 9 + tid];
    if (tid < 3) T[tid] = trans[n * 3 + tid];
    if (tid < NHEAD) {
        float x = hw[tid];
        float sp = (x > 20.f) ? x : log1pf(expf(x));
        pw[tid] = PWCONST * sp;
    }
    __syncthreads();
    for (int i = tid; i < 192; i += 128) {
        int h = i / 16, c = i % 16;
        g_qf[((size_t)n * NHEAD + h) * 28 + c] = p[i] * 0.25f;
        g_kf[((size_t)n * NHEAD + h) * 28 + c] = p[192 + i];
        g_vcat[((size_t)n * NHEAD + h) * 40 + c] = p[384 + i];
    }
    if (tid < 12) {
        int h = tid;
        float sq = 0.f;
        float pwh = pw[h];
        for (int pp = 0; pp < PQKN; pp++) {
            float lx = p[576 + h * 12 + 0 + pp] + bqp[h * 12 + 0 + pp];
            float ly = p[576 + h * 12 + 4 + pp] + bqp[h * 12 + 4 + pp];
            float lz = p[576 + h * 12 + 8 + pp] + bqp[h * 12 + 8 + pp];
            float gx = R[0] * lx + R[1] * ly + R[2] * lz + T[0];
            float gy = R[3] * lx + R[4] * ly + R[5] * lz + T[1];
            float gz = R[6] * lx + R[7] * ly + R[8] * lz + T[2];
            float* qo = &g_qf[((size_t)n * NHEAD + h) * 28 + 16 + pp * 3];
            qo[0] = pwh * gx; qo[1] = pwh * gy; qo[2] = pwh * gz;
            sq += gx * gx + gy * gy + gz * gz;
        }
        g_gq[n * NHEAD + h] = -0.5f * pwh * sq;
    } else if (tid < 24) {
        int h = tid - 12;
        float sq = 0.f;
        for (int pp = 0; pp < PQKN; pp++) {
            float lx = p[720 + h * 12 + 0 + pp] + bkp[h * 12 + 0 + pp];
            float ly = p[720 + h * 12 + 4 + pp] + bkp[h * 12 + 4 + pp];
            float lz = p[720 + h * 12 + 8 + pp] + bkp[h * 12 + 8 + pp];
            float gx = R[0] * lx + R[1] * ly + R[2] * lz + T[0];
            float gy = R[3] * lx + R[4] * ly + R[5] * lz + T[1];
            float gz = R[6] * lx + R[7] * ly + R[8] * lz + T[2];
            float* ko = &g_kf[((size_t)n * NHEAD + h) * 28 + 16 + pp * 3];
            ko[0] = gx; ko[1] = gy; ko[2] = gz;
            sq += gx * gx + gy * gy + gz * gz;
        }
        g_gk[n * NHEAD + h] = -0.5f * pw[h] * sq;
    } else if (tid < 36) {
        int h = tid - 24;
        for (int pp = 0; pp < PVN; pp++) {
            float lx = p[864 + h * 24 + 0 + pp] + bvp[h * 24 + 0 + pp];
            float ly = p[864 + h * 24 + 8 + pp] + bvp[h * 24 + 8 + pp];
            float lz = p[864 + h * 24 + 16 + pp] + bvp[h * 24 + 16 + pp];
            float gx = R[0] * lx + R[1] * ly + R[2] * lz + T[0];
            float gy = R[3] * lx + R[4] * ly + R[5] * lz + T[1];
            float gz = R[6] * lx + R[7] * ly + R[8] * lz + T[2];
            float* vo = &g_vcat[((size_t)n * NHEAD + h) * 40 + 16 + pp * 3];
            vo[0] = gx; vo[1] = gy; vo[2] = gz;
        }
    }
}

// ---------------- 4: pair bias (z pass #1) -> g_att[h][q][k] ----------------
// v6 (verified 88us): block = (q, 256-k slice), 128 threads, 2 k per thread.
__global__ void __launch_bounds__(128) k_bbias(const float* __restrict__ z,
                                               const float* __restrict__ wb,
                                               const float* __restrict__ bb) {
    int q = blockIdx.y;
    int k0 = blockIdx.x * 256;
    int tid = threadIdx.x;
    __shared__ __align__(16) float zbuf[256 * 36];      // 36.9 KB
    __shared__ __align__(16) float wbs[CZDIM * NHEAD];  // 6 KB
    __shared__ float bbs[NHEAD];
    for (int i = tid; i < CZDIM * NHEAD; i += 128) wbs[i] = wb[i];
    if (tid < NHEAD) bbs[tid] = bb[tid];

    const float4* zg4 = (const float4*)z + ((size_t)q * NRES + k0) * 32;

    unsigned long long acc[2][6];
#pragma unroll
    for (int kc = 0; kc < 2; kc++)
#pragma unroll
        for (int p = 0; p < 6; p++) acc[kc][p] = 0ull;

    for (int cc = 0; cc < 4; cc++) {
        __syncthreads();
#pragma unroll
        for (int i = 0; i < 16; i++) {
            int f = tid + i * 128;
            int row = f >> 3, c4 = f & 7;
            *(float4*)&zbuf[row * 36 + c4 * 4] = zg4[(size_t)row * 32 + cc * 8 + c4];
        }
        __syncthreads();
#pragma unroll
        for (int ch4 = 0; ch4 < 8; ch4++) {
            float4 za = *(const float4*)&zbuf[tid * 36 + ch4 * 4];
            float4 zb = *(const float4*)&zbuf[(tid + 128) * 36 + ch4 * 4];
            float z0v[4] = {za.x, za.y, za.z, za.w};
            float z1v[4] = {zb.x, zb.y, zb.z, zb.w};
            int cbase = cc * 32 + ch4 * 4;
#pragma unroll
            for (int e = 0; e < 4; e++) {
                const unsigned long long* wp =
                    (const unsigned long long*)(wbs + (cbase + e) * NHEAD);
                unsigned long long w0 = wp[0], w1 = wp[1], w2 = wp[2],
                                   w3 = wp[3], w4 = wp[4], w5 = wp[5];
                unsigned long long zp0, zp1;
                PACK2(zp0, z0v[e], z0v[e]);
                PACK2(zp1, z1v[e], z1v[e]);
                FFMA2(acc[0][0], zp0, w0, acc[0][0]);
                FFMA2(acc[0][1], zp0, w1, acc[0][1]);
                FFMA2(acc[0][2], zp0, w2, acc[0][2]);
                FFMA2(acc[0][3], zp0, w3, acc[0][3]);
                FFMA2(acc[0][4], zp0, w4, acc[0][4]);
                FFMA2(acc[0][5], zp0, w5, acc[0][5]);
                FFMA2(acc[1][0], zp1, w0, acc[1][0]);
                FFMA2(acc[1][1], zp1, w1, acc[1][1]);
                FFMA2(acc[1][2], zp1, w2, acc[1][2]);
                FFMA2(acc[1][3], zp1, w3, acc[1][3]);
                FFMA2(acc[1][4], zp1, w4, acc[1][4]);
                FFMA2(acc[1][5], zp1, w5, acc[1][5]);
            }
        }
    }
#pragma unroll
    for (int kc = 0; kc < 2; kc++) {
        int k = k0 + kc * 128 + tid;
#pragma unroll
        for (int p = 0; p < 6; p++) {
            float lo, hi;
            UNPACK2(lo, hi, acc[kc][p]);
            g_att[((size_t)(2 * p) * NRES + q) * NRES + k] = lo + bbs[2 * p];
            g_att[((size_t)(2 * p + 1) * NRES + q) * NRES + k] = hi + bbs[2 * p + 1];
        }
    }
}

// ---------------- 5: logits (28-dim bilinear + additive) in-place ----------------
__global__ void __launch_bounds__(256) k_logits(const float* __restrict__ mask) {
    int h = blockIdx.z, q0 = blockIdx.y * 64, k0 = blockIdx.x * 64;
    __shared__ float Qs[28][64], Ks[28][64];
    __shared__ float gqs[64], gks[64], mqs[64], mks[64];
    int tid = threadIdx.x;
    for (int i = tid; i < 64 * 28; i += 256) {
        int r = i / 28, d = i % 28;
        Qs[d][r] = g_qf[((size_t)(q0 + r) * NHEAD + h) * 28 + d];
        Ks[d][r] = g_kf[((size_t)(k0 + r) * NHEAD + h) * 28 + d];
    }
    if (tid < 64) {
        gqs[tid] = g_gq[(q0 + tid) * NHEAD + h];
        mqs[tid] = mask[q0 + tid];
    } else if (tid < 128) {
        int r = tid - 64;
        gks[r] = g_gk[(k0 + r) * NHEAD + h];
        mks[r] = mask[k0 + r];
    }
    __syncthreads();
    int tx = tid % 16, ty = tid / 16;
    float acc[4][4] = {};
#pragma unroll
    for (int d = 0; d < 28; d++) {
        float4 a4 = *(const float4*)&Qs[d][ty * 4];
        float4 b4 = *(const float4*)&Ks[d][tx * 4];
        float av[4] = {a4.x, a4.y, a4.z, a4.w};
        float bv[4] = {b4.x, b4.y, b4.z, b4.w};
#pragma unroll
        for (int i = 0; i < 4; i++)
#pragma unroll
            for (int j = 0; j < 4; j++) acc[i][j] += av[i] * bv[j];
    }
#pragma unroll
    for (int i = 0; i < 4; i++) {
        int r = ty * 4 + i;
        size_t base = ((size_t)h * NRES + (q0 + r)) * NRES + k0 + tx * 4;
        float4 bbv = *(const float4*)&g_att[base];
        float gq = gqs[r], mq = mqs[r];
        float4 o;
        o.x = (bbv.x + acc[i][0] + gq + gks[tx * 4 + 0] + INFV * (mq * mks[tx * 4 + 0] - 1.f)) * RSQRT3;
        o.y = (bbv.y + acc[i][1] + gq + gks[tx * 4 + 1] + INFV * (mq * mks[tx * 4 + 1] - 1.f)) * RSQRT3;
        o.z = (bbv.z + acc[i][2] + gq + gks[tx * 4 + 2] + INFV * (mq * mks[tx * 4 + 2] - 1.f)) * RSQRT3;
        o.w = (bbv.w + acc[i][3] + gq + gks[tx * 4 + 3] + INFV * (mq * mks[tx * 4 + 3] - 1.f)) * RSQRT3;
        *(float4*)&g_att[base] = o;
    }
}

// ---------------- 6+7 fused: softmax (warp/row) + o_pair ----------------
__global__ void __launch_bounds__(256) k_opair(const float* __restrict__ z) {
    int q = blockIdx.x;
    int tid = threadIdx.x;
    int tx = tid % 32, ty = tid / 32;  // (32,8)
    __shared__ __align__(16) float a_s[NHEAD * NRES];  // 36 KB, reused as reduce buffer
    for (int i = tid; i < NHEAD * NRES; i += 256)
        a_s[i] = g_att[((size_t)(i / NRES) * NRES + q) * NRES + (i % NRES)];
    __syncthreads();
    // softmax each (h,q) row in smem; warp ty handles rows ty, ty+8
    for (int hh = ty; hh < NHEAD; hh += 8) {
        float* row = &a_s[hh * NRES];
        float v[24];
        float m = -1e30f;
#pragma unroll
        for (int i = 0; i < 24; i++) { v[i] = row[tx + i * 32]; m = fmaxf(m, v[i]); }
#pragma unroll
        for (int s = 16; s > 0; s >>= 1) m = fmaxf(m, __shfl_xor_sync(0xffffffffu, m, s));
        float sum = 0.f;
#pragma unroll
        for (int i = 0; i < 24; i++) { v[i] = __expf(v[i] - m); sum += v[i]; }
#pragma unroll
        for (int s = 16; s > 0; s >>= 1) sum += __shfl_xor_sync(0xffffffffu, sum, s);
        float inv = 1.f / sum;
        float* grow = &g_att[((size_t)hh * NRES + q) * NRES];
#pragma unroll
        for (int i = 0; i < 24; i++) {
            float a = v[i] * inv;
            row[tx + i * 32] = a;
            grow[tx + i * 32] = a;   // write back for k_ov
        }
    }
    __syncthreads();
    unsigned long long acc2[NHEAD][2];
#pragma unroll
    for (int h = 0; h < NHEAD; h++) { acc2[h][0] = 0ull; acc2[h][1] = 0ull; }
    const ulonglong2* zr = (const ulonglong2*)(z + (size_t)q * NRES * CZDIM);
    for (int k = ty; k < NRES; k += 16) {
        ulonglong2 zv0 = zr[k * 32 + tx];
        ulonglong2 zv1 = zr[(k + 8) * 32 + tx];
#pragma unroll
        for (int h = 0; h < NHEAD; h++) {
            float ah = a_s[h * NRES + k];
            unsigned long long aa;
            PACK2(aa, ah, ah);
            FFMA2(acc2[h][0], aa, zv0.x, acc2[h][0]);
            FFMA2(acc2[h][1], aa, zv0.y, acc2[h][1]);
        }
#pragma unroll
        for (int h = 0; h < NHEAD; h++) {
            float ah = a_s[h * NRES + k + 8];
            unsigned long long aa;
            PACK2(aa, ah, ah);
            FFMA2(acc2[h][0], aa, zv1.x, acc2[h][0]);
            FFMA2(acc2[h][1], aa, zv1.y, acc2[h][1]);
        }
    }
    // tree reduce over ty (8 -> 1) in 3 rounds; slot stride 50 floats
    unsigned long long* red = (unsigned long long*)a_s;
    __syncthreads();
    if (ty >= 4) {
        unsigned long long* d = red + ((ty - 4) * 32 + tx) * 25;
#pragma unroll
        for (int h = 0; h < NHEAD; h++) { d[h * 2] = acc2[h][0]; d[h * 2 + 1] = acc2[h][1]; }
    }
    __syncthreads();
    if (ty < 4) {
        const unsigned long long* d = red + (ty * 32 + tx) * 25;
#pragma unroll
        for (int h = 0; h < NHEAD; h++) {
            ADD2(acc2[h][0], acc2[h][0], d[h * 2]);
            ADD2(acc2[h][1], acc2[h][1], d[h * 2 + 1]);
        }
    }
    __syncthreads();
    if (ty >= 2 && ty < 4) {
        unsigned long long* d = red + ((ty - 2) * 32 + tx) * 25;
#pragma unroll
        for (int h = 0; h < NHEAD; h++) { d[h * 2] = acc2[h][0]; d[h * 2 + 1] = acc2[h][1]; }
    }
    __syncthreads();
    if (ty < 2) {
        const unsigned long long* d = red + (ty * 32 + tx) * 25;
#pragma unroll
        for (int h = 0; h < NHEAD; h++) {
            ADD2(acc2[h][0], acc2[h][0], d[h * 2]);
            ADD2(acc2[h][1], acc2[h][1], d[h * 2 + 1]);
        }
    }
    __syncthreads();
    if (ty == 1) {
        unsigned long long* d = red + tx * 25;
#pragma unroll
        for (int h = 0; h < NHEAD; h++) { d[h * 2] = acc2[h][0]; d[h * 2 + 1] = acc2[h][1]; }
    }
    __syncthreads();
    if (ty == 0) {
        const unsigned long long* d = red + tx * 25;
        float* out = &g_cat[(size_t)q * CATDIM + 576];
#pragma unroll
        for (int h = 0; h < NHEAD; h++) {
            ADD2(acc2[h][0], acc2[h][0], d[h * 2]);
            ADD2(acc2[h][1], acc2[h][1], d[h * 2 + 1]);
            float4 o;
            UNPACK2(o.x, o.y, acc2[h][0]);
            UNPACK2(o.z, o.w, acc2[h][1]);
            *(float4*)&out[h * CZDIM + tx * 4] = o;
        }
    }
}

// ---------------- 8: o + o_pt, BQ=32, [k][q] a-tile + f32x2 ----------------
__global__ void __launch_bounds__(320) k_ov() {
    int h = blockIdx.y;
    int q0 = blockIdx.x * 32;
    __shared__ float a_t[64 * 37];   // [kk][q pad 37]
    __shared__ float v_t[64 * 40];   // [kk][c]
    int tid = threadIdx.x;           // 320
    int cg = tid % 20, qg = tid / 20;
    unsigned long long acc[2] = {0ull, 0ull};
    for (int k0 = 0; k0 < NRES; k0 += 64) {
        if (k0) __syncthreads();
        for (int i = tid; i < 2048; i += 320) {
            int kk = i & 63, r = i >> 6;
            a_t[kk * 37 + r] = g_att[((size_t)h * NRES + q0 + r) * NRES + k0 + kk];
        }
        for (int i = tid; i < 2560; i += 320) {
            int r = i / 40, j = i % 40;
            v_t[r * 40 + j] = g_vcat[((size_t)(k0 + r) * NHEAD + h) * 40 + j];
        }
        __syncthreads();
#pragma unroll 8
        for (int kk = 0; kk < 64; kk++) {
            float a0 = a_t[kk * 37 + qg * 2];
            float a1 = a_t[kk * 37 + qg * 2 + 1];
            unsigned long long v2 = *(const unsigned long long*)&v_t[kk * 40 + cg * 2];
            unsigned long long d0, d1;
            PACK2(d0, a0, a0); FFMA2(acc[0], d0, v2, acc[0]);
            PACK2(d1, a1, a1); FFMA2(acc[1], d1, v2, acc[1]);
        }
    }
    int c = cg * 2;
#pragma unroll
    for (int r = 0; r < 2; r++) {
        int q = q0 + qg * 2 + r;
        float lo, hi;
        UNPACK2(lo, hi, acc[r]);
        if (c < 16) {
            g_cat[(size_t)q * CATDIM + h * 16 + c] = lo;
            g_cat[(size_t)q * CATDIM + h * 16 + c + 1] = hi;
        } else {
            float* o = &g_opt[((size_t)q * NHEAD + h) * 24];
            o[c - 16] = lo;
            o[c - 15] = hi;
        }
    }
}

// ---------------- 9: rigid-inverse + norms ----------------
__global__ void k_finalize(const float* __restrict__ rot, const float* __restrict__ trans) {
    int q = blockIdx.x;
    int tid = threadIdx.x;  // 96 threads
    __shared__ float R[9], T[3];
    if (tid < 9) R[tid] = rot[q * 9 + tid];
    if (tid < 3) T[tid] = trans[q * 3 + tid];
    __syncthreads();
    int h = tid / 8, pp = tid % 8;
    const float* o = &g_opt[((size_t)q * NHEAD + h) * 24 + pp * 3];
    float dx = o[0] - T[0], dy = o[1] - T[1], dz = o[2] - T[2];
    float lx = R[0] * dx + R[3] * dy + R[6] * dz;
    float ly = R[1] * dx + R[4] * dy + R[7] * dz;
    float lz = R[2] * dx + R[5] * dy + R[8] * dz;
    float nrm = sqrtf(fmaxf(lx * lx + ly * ly + lz * lz, 1e-16f));
    int col = h * 8 + pp;
    float* cr = &g_cat[(size_t)q * CATDIM];
    cr[192 + col] = lx;
    cr[288 + col] = ly;
    cr[384 + col] = lz;
    cr[480 + col] = nrm;
}

// ---------------- launcher ----------------
extern "C" void kernel_launch(void* const* d_in, const int* in_sizes, int n_in,
                              void* d_out, int out_size) {
    const float* s     = (const float*)d_in[0];
    const float* z     = (const float*)d_in[1];
    const float* mask  = (const float*)d_in[2];
    const float* rot   = (const float*)d_in[3];
    const float* trans = (const float*)d_in[4];
    const float* w_q   = (const float*)d_in[5];
    const float* w_k   = (const float*)d_in[6];
    const float* w_v   = (const float*)d_in[7];
    const float* w_qp  = (const float*)d_in[8];
    const float* b_qp  = (const float*)d_in[9];
    const float* w_kp  = (const float*)d_in[10];
    const float* b_kp  = (const float*)d_in[11];
    const float* w_vp  = (const float*)d_in[12];
    const float* b_vp  = (const float*)d_in[13];
    const float* w_b   = (const float*)d_in[14];
    const float* b_b   = (const float*)d_in[15];
    const float* hw    = (const float*)d_in[16];
    const float* w_out = (const float*)d_in[17];
    const float* b_out = (const float*)d_in[18];
    float* out = (float*)d_out;

    float *p_wcat, *p_proj, *p_cat, *p_part;
    cudaGetSymbolAddress((void**)&p_wcat, g_wcat);
    cudaGetSymbolAddress((void**)&p_proj, g_proj);
    cudaGetSymbolAddress((void**)&p_cat, g_cat);
    cudaGetSymbolAddress((void**)&p_part, g_part);

    k_concat_w<<<(CSDIM * PROJD + 255) / 256, 256>>>(w_q, w_k, w_v, w_qp, w_kp, w_vp);
    k_sgemm<<<dim3(PROJD / 64, NRES / 64, 1), 256>>>(s, CSDIM, p_wcat, p_proj,
                                                     NRES, PROJD, CSDIM);
    k_prep<<<NRES, 128>>>(b_qp, b_kp, b_vp, rot, trans, hw);
    k_bbias<<<dim3(3, NRES), 128>>>(z, w_b, b_b);
    k_logits<<<dim3(NRES / 64, NRES / 64, NHEAD), 256>>>(mask);
    k_opair<<<NRES, 256>>>(z);     // fused softmax + o_pair (writes softmax'd att back)
    k_ov<<<dim3(NRES / 32, NHEAD), 320>>>();
    k_finalize<<<NRES, 96>>>(rot, trans);
    // final GEMM: split-K = 3 (2112 = 3 * 704) in one 3D launch, then reduce + bias
    k_sgemm<<<dim3(CSDIM / 64, NRES / 64, 3), 256>>>(p_cat, CATDIM, w_out,
                                                     p_part, NRES, CSDIM, 704);
    k_reduce3<<<NRES * CSDIM / 256, 256>>>(out, b_out);
}